// round 5
// baseline (speedup 1.0000x reference)
#include <cuda_runtime.h>
#include <math.h>

#define BSZ   8
#define TSEQ  2048
#define CDIM  1024
#define HD    64

typedef unsigned long long ull;

// scratch for projected q, k, v  (4 MB each)
__device__ float g_q[BSZ * TSEQ * HD];
__device__ float g_k[BSZ * TSEQ * HD];
__device__ float g_v[BSZ * TSEQ * HD];

// ---- packed f32x2 helpers (sm_103a dual-rate fp32) -------------------------
__device__ __forceinline__ ull pk2(float lo, float hi) {
    ull r; asm("mov.b64 %0, {%1, %2};" : "=l"(r) : "f"(lo), "f"(hi)); return r;
}
__device__ __forceinline__ ull dup2(float v) { return pk2(v, v); }
__device__ __forceinline__ ull ffma2(ull a, ull b, ull c) {
    ull d; asm("fma.rn.f32x2 %0, %1, %2, %3;" : "=l"(d) : "l"(a), "l"(b), "l"(c)); return d;
}
__device__ __forceinline__ ull fmul2(ull a, ull b) {
    ull d; asm("mul.rn.f32x2 %0, %1, %2;" : "=l"(d) : "l"(a), "l"(b)); return d;
}
__device__ __forceinline__ float2 up2(ull v) {
    float lo, hi; asm("mov.b64 {%0, %1}, %2;" : "=f"(lo), "=f"(hi) : "l"(v));
    float2 f; f.x = lo; f.y = hi; return f;
}

// ---------------------------------------------------------------------------
// Kernel 1: QKV projection (R3 version — best measured, 139us).
// M=16384, N=192(3x64), K=1024. BM=128, BN=64, BK=16, 256 threads, 8x4 tile.
// Double-buffered smem, packed-A LDS.64, FFMA2 inner loop.
// ---------------------------------------------------------------------------
__global__ __launch_bounds__(256) void qkv_proj_kernel(
    const float* __restrict__ x,
    const float* __restrict__ W,
    const float* __restrict__ b)
{
    __shared__ float As[2][16][132];   // [buf][k][row]
    __shared__ float Bs[2][16][68];    // [buf][k][col]

    const int bm  = blockIdx.x;
    const int bn  = blockIdx.y;
    const int tid = threadIdx.x;

    const int tr = tid >> 4;
    const int tc = tid & 15;
    const int row0 = tr * 8;
    const int col0 = tc * 4;

    const float* xblk = x + (size_t)bm * 128 * CDIM;
    const float* wblk = W + bn * 64;

    const int lr0 = tid >> 2;
    const int lkk = (tid & 3) * 4;
    const int bkr = tid >> 4;
    const int bnc = (tid & 15) * 4;

    ull acc2[4][4];
#pragma unroll
    for (int i = 0; i < 4; i++)
#pragma unroll
        for (int j = 0; j < 4; j++) acc2[i][j] = 0ULL;

    {
        float4 a0 = *reinterpret_cast<const float4*>(xblk + (size_t)lr0 * CDIM + lkk);
        float4 a1 = *reinterpret_cast<const float4*>(xblk + (size_t)(lr0 + 64) * CDIM + lkk);
        float4 bw = *reinterpret_cast<const float4*>(wblk + (size_t)bkr * 192 + bnc);
        As[0][lkk + 0][lr0] = a0.x; As[0][lkk + 1][lr0] = a0.y;
        As[0][lkk + 2][lr0] = a0.z; As[0][lkk + 3][lr0] = a0.w;
        As[0][lkk + 0][lr0 + 64] = a1.x; As[0][lkk + 1][lr0 + 64] = a1.y;
        As[0][lkk + 2][lr0 + 64] = a1.z; As[0][lkk + 3][lr0 + 64] = a1.w;
        *reinterpret_cast<float4*>(&Bs[0][bkr][bnc]) = bw;
    }
    __syncthreads();

    for (int c = 0; c < 64; c++) {
        const int cur = c & 1;
        if (c < 63) {
            const int k0 = (c + 1) * 16;
            float4 a0 = *reinterpret_cast<const float4*>(xblk + (size_t)lr0 * CDIM + k0 + lkk);
            float4 a1 = *reinterpret_cast<const float4*>(xblk + (size_t)(lr0 + 64) * CDIM + k0 + lkk);
            float4 bw = *reinterpret_cast<const float4*>(wblk + (size_t)(k0 + bkr) * 192 + bnc);
            const int nb = cur ^ 1;
            As[nb][lkk + 0][lr0] = a0.x; As[nb][lkk + 1][lr0] = a0.y;
            As[nb][lkk + 2][lr0] = a0.z; As[nb][lkk + 3][lr0] = a0.w;
            As[nb][lkk + 0][lr0 + 64] = a1.x; As[nb][lkk + 1][lr0 + 64] = a1.y;
            As[nb][lkk + 2][lr0 + 64] = a1.z; As[nb][lkk + 3][lr0 + 64] = a1.w;
            *reinterpret_cast<float4*>(&Bs[nb][bkr][bnc]) = bw;
        }

#pragma unroll
        for (int kk = 0; kk < 16; kk++) {
            ull aP0 = *reinterpret_cast<const ull*>(&As[cur][kk][row0 + 0]);
            ull aP1 = *reinterpret_cast<const ull*>(&As[cur][kk][row0 + 2]);
            ull aP2 = *reinterpret_cast<const ull*>(&As[cur][kk][row0 + 4]);
            ull aP3 = *reinterpret_cast<const ull*>(&As[cur][kk][row0 + 6]);
            float4 bf = *reinterpret_cast<const float4*>(&Bs[cur][kk][col0]);
            ull b0 = dup2(bf.x), b1 = dup2(bf.y), b2 = dup2(bf.z), b3 = dup2(bf.w);
            acc2[0][0] = ffma2(aP0, b0, acc2[0][0]);
            acc2[0][1] = ffma2(aP0, b1, acc2[0][1]);
            acc2[0][2] = ffma2(aP0, b2, acc2[0][2]);
            acc2[0][3] = ffma2(aP0, b3, acc2[0][3]);
            acc2[1][0] = ffma2(aP1, b0, acc2[1][0]);
            acc2[1][1] = ffma2(aP1, b1, acc2[1][1]);
            acc2[1][2] = ffma2(aP1, b2, acc2[1][2]);
            acc2[1][3] = ffma2(aP1, b3, acc2[1][3]);
            acc2[2][0] = ffma2(aP2, b0, acc2[2][0]);
            acc2[2][1] = ffma2(aP2, b1, acc2[2][1]);
            acc2[2][2] = ffma2(aP2, b2, acc2[2][2]);
            acc2[2][3] = ffma2(aP2, b3, acc2[2][3]);
            acc2[3][0] = ffma2(aP3, b0, acc2[3][0]);
            acc2[3][1] = ffma2(aP3, b1, acc2[3][1]);
            acc2[3][2] = ffma2(aP3, b2, acc2[3][2]);
            acc2[3][3] = ffma2(aP3, b3, acc2[3][3]);
        }
        __syncthreads();
    }

    float bias[4];
#pragma unroll
    for (int j = 0; j < 4; j++) bias[j] = b[bn * 64 + col0 + j];

    float* outbuf = (bn == 0) ? g_k : (bn == 1) ? g_q : g_v;
#pragma unroll
    for (int i = 0; i < 8; i++) {
        int ip = i >> 1;
        float2 f0 = up2(acc2[ip][0]);
        float2 f1 = up2(acc2[ip][1]);
        float2 f2 = up2(acc2[ip][2]);
        float2 f3 = up2(acc2[ip][3]);
        float4 o;
        o.x = ((i & 1) ? f0.y : f0.x) + bias[0];
        o.y = ((i & 1) ? f1.y : f1.x) + bias[1];
        o.z = ((i & 1) ? f2.y : f2.x) + bias[2];
        o.w = ((i & 1) ? f3.y : f3.x) + bias[3];
        *reinterpret_cast<float4*>(
            outbuf + (size_t)(bm * 128 + row0 + i) * HD + col0) = o;
    }
}

// ---------------------------------------------------------------------------
// Kernel 2: causal flash attention — R2 math, reshaped for occupancy.
// 128-thread CTAs, 32-row q-tiles; block does q-tiles (bx, 63-bx) -> exactly
// 33 key-tile units each. Grid (64, 8) = 512 blocks -> 3-4 CTAs/SM.
// Per key tile: GEMM1 S=Q@K^T (4x4 micro, FFMA2), register softmax,
// P in own smem buffer, GEMM2 O+=P@V.  48 KB smem/CTA.
// ---------------------------------------------------------------------------
#define AQM 32   // q rows per tile
#define AKN 64   // keys per tile

__global__ __launch_bounds__(128) void attn_kernel(float* __restrict__ out)
{
    __shared__ float q_s[64][AQM];        // [d][r^swz], pre-scaled
    __shared__ float k_s[64][AKN];        // [d][j^swz]
    __shared__ float v_s[AKN][64];        // [j][c] row-major
    __shared__ float p_s[AKN][AQM];       // [j][r^swz]

    const int tid = threadIdx.x;
    const int tr = tid >> 4, tc = tid & 15;   // tr 0..7, tc 0..15
    const int r0 = tr * 4, c0 = tc * 4, j0 = tc * 4;
    const int bb = blockIdx.y;

    const float* kg = g_k + (size_t)bb * TSEQ * HD;
    const float* vg = g_v + (size_t)bb * TSEQ * HD;

    for (int half = 0; half < 2; half++) {
        const int qt = half ? (63 - (int)blockIdx.x) : (int)blockIdx.x;
        const int qrow0 = qt * AQM;
        const float* qg = g_q + ((size_t)bb * TSEQ + qrow0) * HD;

        __syncthreads();   // previous half's q_s readers done
        // load Q tile (32x64) transposed + swizzled + pre-scaled: 512 float4 / 128 thr
#pragma unroll
        for (int it = 0; it < 4; it++) {
            int idx = it * 128 + tid;
            int r = idx >> 4;                 // 0..31
            int d = (idx & 15) << 2;          // 0..60
            float4 v4 = *reinterpret_cast<const float4*>(qg + (size_t)r * HD + d);
            int sw_r = r ^ (((d >> 2) & 7) << 2);
            q_s[d + 0][sw_r] = v4.x * 0.125f;
            q_s[d + 1][sw_r] = v4.y * 0.125f;
            q_s[d + 2][sw_r] = v4.z * 0.125f;
            q_s[d + 3][sw_r] = v4.w * 0.125f;
        }

        ull o2[2][4] = {{0ULL,0ULL,0ULL,0ULL},{0ULL,0ULL,0ULL,0ULL}};
        float m[4] = {-1e30f, -1e30f, -1e30f, -1e30f};
        float l[4] = {0.f, 0.f, 0.f, 0.f};

        const int n_kt = (qt + 2) >> 1;       // key tiles needed (64 keys each)

        for (int kt = 0; kt < n_kt; kt++) {
            const int t0 = kt * AKN;
            __syncthreads();   // prev tile's k_s/v_s readers done
            // load K (transposed+swizzled) and V (row-major): 1024 float4 each / 128 thr
#pragma unroll
            for (int it = 0; it < 8; it++) {
                int idx = it * 128 + tid;
                int r = idx >> 4;             // 0..63
                int d = (idx & 15) << 2;
                float4 k4 = *reinterpret_cast<const float4*>(
                    kg + (size_t)(t0 + r) * HD + d);
                int sw_r = r ^ (((d >> 2) & 7) << 2);
                k_s[d + 0][sw_r] = k4.x;
                k_s[d + 1][sw_r] = k4.y;
                k_s[d + 2][sw_r] = k4.z;
                k_s[d + 3][sw_r] = k4.w;
                *reinterpret_cast<float4*>(&v_s[r][d]) =
                    *reinterpret_cast<const float4*>(vg + (size_t)(t0 + r) * HD + d);
            }
            __syncthreads();

            // ---- GEMM1: S = Q @ K^T (rows paired in f32x2) ----
            ull s2[2][4] = {{0ULL,0ULL,0ULL,0ULL},{0ULL,0ULL,0ULL,0ULL}};
#pragma unroll 8
            for (int d = 0; d < 64; d++) {
                int sw  = ((d >> 2) & 7) << 2;
                int r0s = r0 ^ sw;
                ull a01 = *reinterpret_cast<const ull*>(&q_s[d][r0s]);
                ull a23 = *reinterpret_cast<const ull*>(&q_s[d][r0s + 2]);
                float4 bv = *reinterpret_cast<const float4*>(&k_s[d][j0 ^ sw]);
                ull b0 = dup2(bv.x), b1 = dup2(bv.y), b2 = dup2(bv.z), b3 = dup2(bv.w);
                s2[0][0] = ffma2(a01, b0, s2[0][0]);
                s2[0][1] = ffma2(a01, b1, s2[0][1]);
                s2[0][2] = ffma2(a01, b2, s2[0][2]);
                s2[0][3] = ffma2(a01, b3, s2[0][3]);
                s2[1][0] = ffma2(a23, b0, s2[1][0]);
                s2[1][1] = ffma2(a23, b1, s2[1][1]);
                s2[1][2] = ffma2(a23, b2, s2[1][2]);
                s2[1][3] = ffma2(a23, b3, s2[1][3]);
            }

            float s[4][4];
#pragma unroll
            for (int ip = 0; ip < 2; ip++)
#pragma unroll
                for (int j = 0; j < 4; j++) {
                    float2 f = up2(s2[ip][j]);
                    s[2 * ip + 0][j] = f.x;
                    s[2 * ip + 1][j] = f.y;
                }

            if (kt == n_kt - 1) {   // tile touching/crossing the diagonal
#pragma unroll
                for (int i = 0; i < 4; i++)
#pragma unroll
                    for (int j = 0; j < 4; j++)
                        if (t0 + j0 + j > qrow0 + r0 + i) s[i][j] = -1e30f;
            }

            // ---- streaming softmax (row reduce over 16 tc-lanes) ----
            float mn[4], corr[4];
#pragma unroll
            for (int i = 0; i < 4; i++) {
                float mx = fmaxf(fmaxf(s[i][0], s[i][1]), fmaxf(s[i][2], s[i][3]));
#pragma unroll
                for (int o = 1; o < 16; o <<= 1)
                    mx = fmaxf(mx, __shfl_xor_sync(0xffffffffu, mx, o));
                mn[i]   = fmaxf(m[i], mx);
                corr[i] = __expf(m[i] - mn[i]);
                m[i]    = mn[i];
            }

            const int swp = (tc & 7) << 2;   // swizzle for p rows j0..j0+3
#pragma unroll
            for (int i = 0; i < 4; i++) {
                float r4 = 0.f;
#pragma unroll
                for (int j = 0; j < 4; j++) {
                    float e = __expf(s[i][j] - mn[i]);
                    r4 += e;
                    p_s[j0 + j][(r0 + i) ^ swp] = e;
                }
#pragma unroll
                for (int o = 1; o < 16; o <<= 1)
                    r4 += __shfl_xor_sync(0xffffffffu, r4, o);
                l[i] = l[i] * corr[i] + r4;
            }

            ull c01 = pk2(corr[0], corr[1]), c23 = pk2(corr[2], corr[3]);
#pragma unroll
            for (int j = 0; j < 4; j++) {
                o2[0][j] = fmul2(o2[0][j], c01);
                o2[1][j] = fmul2(o2[1][j], c23);
            }
            __syncthreads();   // P visible to all

            // ---- GEMM2: O += P @ V ----
#pragma unroll 8
            for (int j = 0; j < AKN; j++) {
                int sw  = ((j >> 2) & 7) << 2;
                int r0s = r0 ^ sw;
                ull a01 = *reinterpret_cast<const ull*>(&p_s[j][r0s]);
                ull a23 = *reinterpret_cast<const ull*>(&p_s[j][r0s + 2]);
                float4 bv = *reinterpret_cast<const float4*>(&v_s[j][c0]);
                ull b0 = dup2(bv.x), b1 = dup2(bv.y), b2 = dup2(bv.z), b3 = dup2(bv.w);
                o2[0][0] = ffma2(a01, b0, o2[0][0]);
                o2[0][1] = ffma2(a01, b1, o2[0][1]);
                o2[0][2] = ffma2(a01, b2, o2[0][2]);
                o2[0][3] = ffma2(a01, b3, o2[0][3]);
                o2[1][0] = ffma2(a23, b0, o2[1][0]);
                o2[1][1] = ffma2(a23, b1, o2[1][1]);
                o2[1][2] = ffma2(a23, b2, o2[1][2]);
                o2[1][3] = ffma2(a23, b3, o2[1][3]);
            }
        }

        // ---- finalize ----
#pragma unroll
        for (int i = 0; i < 4; i++) {
            float inv = 1.f / l[i];
            float2 f0 = up2(o2[i >> 1][0]);
            float2 f1 = up2(o2[i >> 1][1]);
            float2 f2 = up2(o2[i >> 1][2]);
            float2 f3 = up2(o2[i >> 1][3]);
            float4 o;
            o.x = ((i & 1) ? f0.y : f0.x) * inv;
            o.y = ((i & 1) ? f1.y : f1.x) * inv;
            o.z = ((i & 1) ? f2.y : f2.x) * inv;
            o.w = ((i & 1) ? f3.y : f3.x) * inv;
            *reinterpret_cast<float4*>(
                out + ((size_t)bb * TSEQ + qrow0 + r0 + i) * HD + c0) = o;
        }
    }
}

// ---------------------------------------------------------------------------
extern "C" void kernel_launch(void* const* d_in, const int* in_sizes, int n_in,
                              void* d_out, int out_size)
{
    const float* x = (const float*)d_in[0];
    const float* W = (const float*)d_in[1];
    const float* b = (const float*)d_in[2];
    float* out = (float*)d_out;

    (void)in_sizes; (void)n_in; (void)out_size;

    dim3 g1((BSZ * TSEQ) / 128, 3);
    qkv_proj_kernel<<<g1, 256>>>(x, W, b);

    dim3 g2(64, BSZ);
    attn_kernel<<<g2, 128>>>(out);
}

// round 7
// speedup vs baseline: 1.5484x; 1.5484x over previous
#include <cuda_runtime.h>
#include <cuda_bf16.h>
#include <math.h>
#include <stdint.h>

#define BSZ   8
#define TSEQ  2048
#define CDIM  1024
#define HD    64

typedef unsigned long long ull;
typedef unsigned int u32;

// scratch for projected q, k, v  (4 MB each)
__device__ float g_q[BSZ * TSEQ * HD];
__device__ float g_k[BSZ * TSEQ * HD];
__device__ float g_v[BSZ * TSEQ * HD];

// split-bf16 inputs: x (row-major [16384][1024]) and W transposed ([192][1024])
__device__ __align__(16) __nv_bfloat16 g_x_hi[BSZ * TSEQ * CDIM];
__device__ __align__(16) __nv_bfloat16 g_x_lo[BSZ * TSEQ * CDIM];
__device__ __align__(16) __nv_bfloat16 g_wt_hi[192 * CDIM];
__device__ __align__(16) __nv_bfloat16 g_wt_lo[192 * CDIM];

// ---- packed f32x2 helpers (SIMT attention) ---------------------------------
__device__ __forceinline__ ull pk2(float lo, float hi) {
    ull r; asm("mov.b64 %0, {%1, %2};" : "=l"(r) : "f"(lo), "f"(hi)); return r;
}
__device__ __forceinline__ ull dup2(float v) { return pk2(v, v); }
__device__ __forceinline__ ull ffma2(ull a, ull b, ull c) {
    ull d; asm("fma.rn.f32x2 %0, %1, %2, %3;" : "=l"(d) : "l"(a), "l"(b), "l"(c)); return d;
}
__device__ __forceinline__ ull fmul2(ull a, ull b) {
    ull d; asm("mul.rn.f32x2 %0, %1, %2;" : "=l"(d) : "l"(a), "l"(b)); return d;
}
__device__ __forceinline__ float2 up2(ull v) {
    float lo, hi; asm("mov.b64 {%0, %1}, %2;" : "=f"(lo), "=f"(hi) : "l"(v));
    float2 f; f.x = lo; f.y = hi; return f;
}

// bf16x2 pack: element0 (low half) = lo, element1 = hi
__device__ __forceinline__ u32 bf2(float lo, float hi) {
    u32 r; asm("cvt.rn.bf16x2.f32 %0, %1, %2;" : "=r"(r) : "f"(hi), "f"(lo));
    return r;
}

// mma.sync m16n8k16 bf16 (arch-neutral HMMA path; ptxas-legal on sm_103)
__device__ __forceinline__ void mma16816(float c[4], const u32 a[4], const u32 b[2]) {
    asm volatile(
        "mma.sync.aligned.m16n8k16.row.col.f32.bf16.bf16.f32 "
        "{%0,%1,%2,%3}, {%4,%5,%6,%7}, {%8,%9}, {%0,%1,%2,%3};"
        : "+f"(c[0]), "+f"(c[1]), "+f"(c[2]), "+f"(c[3])
        : "r"(a[0]), "r"(a[1]), "r"(a[2]), "r"(a[3]), "r"(b[0]), "r"(b[1]));
}

// ---------------------------------------------------------------------------
// Prep kernels: split fp32 -> bf16 hi/lo.
// ---------------------------------------------------------------------------
__global__ __launch_bounds__(256) void wprep_kernel(const float* __restrict__ W)
{
    int idx = blockIdx.x * 256 + threadIdx.x;
    if (idx >= 192 * CDIM) return;
    int n = idx >> 10, k = idx & 1023;
    float w = W[(size_t)k * 192 + n];
    __nv_bfloat16 hi = __float2bfloat16(w);
    g_wt_hi[(size_t)n * CDIM + k] = hi;
    g_wt_lo[(size_t)n * CDIM + k] = __float2bfloat16(w - __bfloat162float(hi));
}

__global__ __launch_bounds__(256) void xprep_kernel(const float* __restrict__ x)
{
    size_t i = ((size_t)blockIdx.x * 256 + threadIdx.x) * 4;
    float4 v = *reinterpret_cast<const float4*>(x + i);
    __nv_bfloat16 h0 = __float2bfloat16(v.x);
    __nv_bfloat16 h1 = __float2bfloat16(v.y);
    __nv_bfloat16 h2 = __float2bfloat16(v.z);
    __nv_bfloat16 h3 = __float2bfloat16(v.w);
    uint2 hv, lv;
    hv.x = bf2(v.x, v.y); hv.y = bf2(v.z, v.w);
    lv.x = bf2(v.x - __bfloat162float(h0), v.y - __bfloat162float(h1));
    lv.y = bf2(v.z - __bfloat162float(h2), v.w - __bfloat162float(h3));
    *reinterpret_cast<uint2*>(g_x_hi + i) = hv;
    *reinterpret_cast<uint2*>(g_x_lo + i) = lv;
}

// ---------------------------------------------------------------------------
// Kernel 1: QKV projection on HMMA (mma.sync bf16, split precision).
// D = x_hi*W_hi + x_lo*W_hi + x_hi*W_lo, fp32 accumulate.
// Grid (3, 128): bn fastest (k/q/v share the x tile in L2).
// CTA: 256 thr = 8 warps (4M x 2N), BM=128, BN=64, BK=32 per stage, 32 stages.
// Warp tile 32x32 = 2 M-atoms x 4 N-atoms of m16n8k16.
// ---------------------------------------------------------------------------
#define XS_STR 34    // bf16 elements per smem row (32 + 2 pad) -> 17 words (odd)

__global__ __launch_bounds__(256) void qkv_mma_kernel(const float* __restrict__ bias)
{
    __shared__ __nv_bfloat16 xs_hi[128 * XS_STR];
    __shared__ __nv_bfloat16 xs_lo[128 * XS_STR];
    __shared__ __nv_bfloat16 ws_hi[64 * XS_STR];
    __shared__ __nv_bfloat16 ws_lo[64 * XS_STR];

    const int tid  = threadIdx.x;
    const int wid  = tid >> 5, lane = tid & 31;
    const int g    = lane >> 2, t = lane & 3;
    const int bn   = blockIdx.x;          // 0=k, 1=q, 2=v
    const int bm   = blockIdx.y;          // 0..127
    const int wm0  = (wid & 3) * 32;
    const int wn0  = (wid >> 2) * 32;

    // loader coords
    const int rx  = tid >> 2;             // 0..63 (x rows done twice: +0, +64)
    const int c8  = (tid & 3) * 8;        // bf16 col offset
    const __nv_bfloat16* xh_src = g_x_hi + ((size_t)(bm * 128 + rx)) * CDIM + c8;
    const __nv_bfloat16* xl_src = g_x_lo + ((size_t)(bm * 128 + rx)) * CDIM + c8;
    const __nv_bfloat16* wh_src = g_wt_hi + ((size_t)(bn * 64 + rx)) * CDIM + c8;   // rx<64 ok: tid>>2 spans 0..63
    const __nv_bfloat16* wl_src = g_wt_lo + ((size_t)(bn * 64 + rx)) * CDIM + c8;

    const u32* xh32 = reinterpret_cast<const u32*>(xs_hi);
    const u32* xl32 = reinterpret_cast<const u32*>(xs_lo);
    const u32* wh32 = reinterpret_cast<const u32*>(ws_hi);
    const u32* wl32 = reinterpret_cast<const u32*>(ws_lo);

    float c[2][4][4];
#pragma unroll
    for (int i = 0; i < 2; i++)
#pragma unroll
        for (int j = 0; j < 4; j++)
#pragma unroll
            for (int q = 0; q < 4; q++) c[i][j][q] = 0.f;

    for (int st = 0; st < 32; st++) {
        const int k0 = st * 32;
        // fetch gmem -> regs (hoisted above barrier)
        uint4 xh0 = *reinterpret_cast<const uint4*>(xh_src + k0);
        uint4 xh1 = *reinterpret_cast<const uint4*>(xh_src + (size_t)64 * CDIM + k0);
        uint4 xl0 = *reinterpret_cast<const uint4*>(xl_src + k0);
        uint4 xl1 = *reinterpret_cast<const uint4*>(xl_src + (size_t)64 * CDIM + k0);
        uint4 wh  = *reinterpret_cast<const uint4*>(wh_src + k0);
        uint4 wl  = *reinterpret_cast<const uint4*>(wl_src + k0);

        __syncthreads();   // prev stage consumers done
        {
            u32* d0 = (u32*)xs_hi + rx * 17 + (c8 >> 1);
            u32* d1 = (u32*)xs_hi + (rx + 64) * 17 + (c8 >> 1);
            d0[0] = xh0.x; d0[1] = xh0.y; d0[2] = xh0.z; d0[3] = xh0.w;
            d1[0] = xh1.x; d1[1] = xh1.y; d1[2] = xh1.z; d1[3] = xh1.w;
            u32* e0 = (u32*)xs_lo + rx * 17 + (c8 >> 1);
            u32* e1 = (u32*)xs_lo + (rx + 64) * 17 + (c8 >> 1);
            e0[0] = xl0.x; e0[1] = xl0.y; e0[2] = xl0.z; e0[3] = xl0.w;
            e1[0] = xl1.x; e1[1] = xl1.y; e1[2] = xl1.z; e1[3] = xl1.w;
            u32* f0 = (u32*)ws_hi + rx * 17 + (c8 >> 1);
            f0[0] = wh.x; f0[1] = wh.y; f0[2] = wh.z; f0[3] = wh.w;
            u32* f1 = (u32*)ws_lo + rx * 17 + (c8 >> 1);
            f1[0] = wl.x; f1[1] = wl.y; f1[2] = wl.z; f1[3] = wl.w;
        }
        __syncthreads();

#pragma unroll
        for (int ks = 0; ks < 2; ks++) {
            const int ko = ks * 8 + t;
            u32 ah[2][4], al[2][4];
#pragma unroll
            for (int i = 0; i < 2; i++) {
                const int rb = (wm0 + i * 16 + g) * 17 + ko;
                ah[i][0] = xh32[rb];
                ah[i][1] = xh32[rb + 8 * 17];
                ah[i][2] = xh32[rb + 4];
                ah[i][3] = xh32[rb + 8 * 17 + 4];
                al[i][0] = xl32[rb];
                al[i][1] = xl32[rb + 8 * 17];
                al[i][2] = xl32[rb + 4];
                al[i][3] = xl32[rb + 8 * 17 + 4];
            }
            u32 bh[4][2], bl[4][2];
#pragma unroll
            for (int j = 0; j < 4; j++) {
                const int nb = (wn0 + j * 8 + g) * 17 + ko;
                bh[j][0] = wh32[nb];
                bh[j][1] = wh32[nb + 4];
                bl[j][0] = wl32[nb];
                bl[j][1] = wl32[nb + 4];
            }
#pragma unroll
            for (int i = 0; i < 2; i++)
#pragma unroll
                for (int j = 0; j < 4; j++) {
                    mma16816(c[i][j], ah[i], bh[j]);
                    mma16816(c[i][j], al[i], bh[j]);
                    mma16816(c[i][j], ah[i], bl[j]);
                }
        }
    }

    // epilogue: +bias, store fp32 to g_k/g_q/g_v
    float* outb = (bn == 0) ? g_k : (bn == 1) ? g_q : g_v;
    const float* brow = bias + bn * 64;
#pragma unroll
    for (int i = 0; i < 2; i++) {
        const int row0 = bm * 128 + wm0 + i * 16 + g;
#pragma unroll
        for (int j = 0; j < 4; j++) {
            const int col = wn0 + j * 8 + 2 * t;
            float2 bz = *reinterpret_cast<const float2*>(brow + col);
            float2 o0, o1;
            o0.x = c[i][j][0] + bz.x;
            o0.y = c[i][j][1] + bz.y;
            o1.x = c[i][j][2] + bz.x;
            o1.y = c[i][j][3] + bz.y;
            *reinterpret_cast<float2*>(outb + (size_t)row0 * HD + col) = o0;
            *reinterpret_cast<float2*>(outb + (size_t)(row0 + 8) * HD + col) = o1;
        }
    }
}

// ---------------------------------------------------------------------------
// Kernel 2: causal flash attention — R2 version verbatim (best measured 188us).
// ---------------------------------------------------------------------------
__global__ __launch_bounds__(256) void attn_kernel(float* __restrict__ out)
{
    __shared__ float q_s[64][64];    // [d][r^swz]  (q pre-scaled)
    __shared__ float kp_s[64][64];   // K: [d][j^swz]; reused as P: [j][r^swz]
    __shared__ float v_s[64][64];    // [j][c] row-major

    const int tid = threadIdx.x;
    const int tr = tid >> 4, tc = tid & 15;
    const int r0 = tr * 4, c0 = tc * 4, j0 = tc * 4;
    const int bb = blockIdx.y;

    const float* kg = g_k + (size_t)bb * TSEQ * HD;
    const float* vg = g_v + (size_t)bb * TSEQ * HD;

    for (int half = 0; half < 2; half++) {
        const int qt = half ? (31 - (int)blockIdx.x) : (int)blockIdx.x;
        const int qrow0 = qt * 64;
        const float* qg = g_q + ((size_t)bb * TSEQ + qrow0) * HD;

        __syncthreads();
#pragma unroll
        for (int it = 0; it < 4; it++) {
            int idx = it * 256 + tid;
            int r = idx >> 4;
            int d = (idx & 15) << 2;
            float4 v4 = *reinterpret_cast<const float4*>(qg + (size_t)r * HD + d);
            int sw_r = r ^ (((d >> 2) & 7) << 2);
            q_s[d + 0][sw_r] = v4.x * 0.125f;
            q_s[d + 1][sw_r] = v4.y * 0.125f;
            q_s[d + 2][sw_r] = v4.z * 0.125f;
            q_s[d + 3][sw_r] = v4.w * 0.125f;
        }

        ull o2[2][4] = {{0ULL,0ULL,0ULL,0ULL},{0ULL,0ULL,0ULL,0ULL}};
        float m[4] = {-1e30f, -1e30f, -1e30f, -1e30f};
        float l[4] = {0.f, 0.f, 0.f, 0.f};

        for (int kt = 0; kt <= qt; kt++) {
            const int t0 = kt * 64;
            __syncthreads();
#pragma unroll
            for (int it = 0; it < 4; it++) {
                int idx = it * 256 + tid;
                int r = idx >> 4;
                int d = (idx & 15) << 2;
                float4 k4 = *reinterpret_cast<const float4*>(
                    kg + (size_t)(t0 + r) * HD + d);
                int sw_r = r ^ (((d >> 2) & 7) << 2);
                kp_s[d + 0][sw_r] = k4.x;
                kp_s[d + 1][sw_r] = k4.y;
                kp_s[d + 2][sw_r] = k4.z;
                kp_s[d + 3][sw_r] = k4.w;
                *reinterpret_cast<float4*>(&v_s[r][d]) =
                    *reinterpret_cast<const float4*>(vg + (size_t)(t0 + r) * HD + d);
            }
            __syncthreads();

            ull s2[2][4] = {{0ULL,0ULL,0ULL,0ULL},{0ULL,0ULL,0ULL,0ULL}};
#pragma unroll 8
            for (int d = 0; d < 64; d++) {
                int sw = ((d >> 2) & 7) << 2;
                float4 a  = *reinterpret_cast<const float4*>(&q_s[d][r0 ^ sw]);
                float4 bv = *reinterpret_cast<const float4*>(&kp_s[d][j0 ^ sw]);
                ull a01 = pk2(a.x, a.y), a23 = pk2(a.z, a.w);
                ull b0 = dup2(bv.x), b1 = dup2(bv.y), b2 = dup2(bv.z), b3 = dup2(bv.w);
                s2[0][0] = ffma2(a01, b0, s2[0][0]);
                s2[0][1] = ffma2(a01, b1, s2[0][1]);
                s2[0][2] = ffma2(a01, b2, s2[0][2]);
                s2[0][3] = ffma2(a01, b3, s2[0][3]);
                s2[1][0] = ffma2(a23, b0, s2[1][0]);
                s2[1][1] = ffma2(a23, b1, s2[1][1]);
                s2[1][2] = ffma2(a23, b2, s2[1][2]);
                s2[1][3] = ffma2(a23, b3, s2[1][3]);
            }

            float s[4][4];
#pragma unroll
            for (int ip = 0; ip < 2; ip++)
#pragma unroll
                for (int j = 0; j < 4; j++) {
                    float2 f = up2(s2[ip][j]);
                    s[2 * ip + 0][j] = f.x;
                    s[2 * ip + 1][j] = f.y;
                }

            if (kt == qt) {
#pragma unroll
                for (int i = 0; i < 4; i++)
#pragma unroll
                    for (int j = 0; j < 4; j++)
                        if (j0 + j > r0 + i) s[i][j] = -1e30f;
            }

            float mn[4], corr[4];
#pragma unroll
            for (int i = 0; i < 4; i++) {
                float mx = fmaxf(fmaxf(s[i][0], s[i][1]), fmaxf(s[i][2], s[i][3]));
#pragma unroll
                for (int o = 1; o < 16; o <<= 1)
                    mx = fmaxf(mx, __shfl_xor_sync(0xffffffffu, mx, o));
                mn[i]   = fmaxf(m[i], mx);
                corr[i] = __expf(m[i] - mn[i]);
                m[i]    = mn[i];
            }

            __syncthreads();

            const int swp = (tc & 7) << 2;
#pragma unroll
            for (int i = 0; i < 4; i++) {
                float r4 = 0.f;
#pragma unroll
                for (int j = 0; j < 4; j++) {
                    float e = __expf(s[i][j] - mn[i]);
                    r4 += e;
                    kp_s[j0 + j][(r0 + i) ^ swp] = e;
                }
#pragma unroll
                for (int o = 1; o < 16; o <<= 1)
                    r4 += __shfl_xor_sync(0xffffffffu, r4, o);
                l[i] = l[i] * corr[i] + r4;
            }

            ull c01 = pk2(corr[0], corr[1]), c23 = pk2(corr[2], corr[3]);
#pragma unroll
            for (int j = 0; j < 4; j++) {
                o2[0][j] = fmul2(o2[0][j], c01);
                o2[1][j] = fmul2(o2[1][j], c23);
            }
            __syncthreads();

#pragma unroll 8
            for (int j = 0; j < 64; j++) {
                int sw = ((j >> 2) & 7) << 2;
                float4 a  = *reinterpret_cast<const float4*>(&kp_s[j][r0 ^ sw]);
                float4 bv = *reinterpret_cast<const float4*>(&v_s[j][c0]);
                ull a01 = pk2(a.x, a.y), a23 = pk2(a.z, a.w);
                ull b0 = dup2(bv.x), b1 = dup2(bv.y), b2 = dup2(bv.z), b3 = dup2(bv.w);
                o2[0][0] = ffma2(a01, b0, o2[0][0]);
                o2[0][1] = ffma2(a01, b1, o2[0][1]);
                o2[0][2] = ffma2(a01, b2, o2[0][2]);
                o2[0][3] = ffma2(a01, b3, o2[0][3]);
                o2[1][0] = ffma2(a23, b0, o2[1][0]);
                o2[1][1] = ffma2(a23, b1, o2[1][1]);
                o2[1][2] = ffma2(a23, b2, o2[1][2]);
                o2[1][3] = ffma2(a23, b3, o2[1][3]);
            }
        }

#pragma unroll
        for (int i = 0; i < 4; i++) {
            float inv = 1.f / l[i];
            float2 f0 = up2(o2[i >> 1][0]);
            float2 f1 = up2(o2[i >> 1][1]);
            float2 f2 = up2(o2[i >> 1][2]);
            float2 f3 = up2(o2[i >> 1][3]);
            float4 o;
            o.x = ((i & 1) ? f0.y : f0.x) * inv;
            o.y = ((i & 1) ? f1.y : f1.x) * inv;
            o.z = ((i & 1) ? f2.y : f2.x) * inv;
            o.w = ((i & 1) ? f3.y : f3.x) * inv;
            *reinterpret_cast<float4*>(
                out + ((size_t)bb * TSEQ + qrow0 + r0 + i) * HD + c0) = o;
        }
    }
}

// ---------------------------------------------------------------------------
extern "C" void kernel_launch(void* const* d_in, const int* in_sizes, int n_in,
                              void* d_out, int out_size)
{
    const float* x = (const float*)d_in[0];
    const float* W = (const float*)d_in[1];
    const float* b = (const float*)d_in[2];
    float* out = (float*)d_out;

    (void)in_sizes; (void)n_in; (void)out_size;

    wprep_kernel<<<(192 * CDIM + 255) / 256, 256>>>(W);
    xprep_kernel<<<(BSZ * TSEQ * CDIM) / (4 * 256), 256>>>(x);
    qkv_mma_kernel<<<dim3(3, 128), 256>>>(b);

    dim3 g2(16, BSZ);
    attn_kernel<<<g2, 256>>>(out);
}

// round 8
// speedup vs baseline: 2.4795x; 1.6013x over previous
#include <cuda_runtime.h>
#include <cuda_bf16.h>
#include <math.h>
#include <stdint.h>

#define BSZ   8
#define TSEQ  2048
#define CDIM  1024
#define HD    64

typedef unsigned long long ull;
typedef unsigned int u32;

// split-bf16 x (row-major) and W transposed ([192][1024])
__device__ __align__(16) __nv_bfloat16 g_x_hi[BSZ * TSEQ * CDIM];
__device__ __align__(16) __nv_bfloat16 g_x_lo[BSZ * TSEQ * CDIM];
__device__ __align__(16) __nv_bfloat16 g_wt_hi[192 * CDIM];
__device__ __align__(16) __nv_bfloat16 g_wt_lo[192 * CDIM];

// split-bf16 attention operands (written by qkv kernel)
__device__ __align__(16) __nv_bfloat16 g_qh[BSZ * TSEQ * HD];  // pre-scaled 0.125
__device__ __align__(16) __nv_bfloat16 g_ql[BSZ * TSEQ * HD];
__device__ __align__(16) __nv_bfloat16 g_kh[BSZ * TSEQ * HD];
__device__ __align__(16) __nv_bfloat16 g_kl[BSZ * TSEQ * HD];
__device__ __align__(16) __nv_bfloat16 g_vth[BSZ * HD * TSEQ]; // [b][d][t]
__device__ __align__(16) __nv_bfloat16 g_vtl[BSZ * HD * TSEQ];

// bf16x2 pack: element0 (low 16 bits) = first arg
__device__ __forceinline__ u32 bf2(float lo, float hi) {
    u32 r; asm("cvt.rn.bf16x2.f32 %0, %1, %2;" : "=r"(r) : "f"(hi), "f"(lo));
    return r;
}
// split a pair into hi pack + lo (residual) pack
__device__ __forceinline__ void split2(float a, float b, u32& hi, u32& lo) {
    hi = bf2(a, b);
    float ha = __uint_as_float(hi << 16);
    float hb = __uint_as_float(hi & 0xffff0000u);
    lo = bf2(a - ha, b - hb);
}

__device__ __forceinline__ void mma16816(float c[4], const u32 a[4], const u32 b[2]) {
    asm volatile(
        "mma.sync.aligned.m16n8k16.row.col.f32.bf16.bf16.f32 "
        "{%0,%1,%2,%3}, {%4,%5,%6,%7}, {%8,%9}, {%0,%1,%2,%3};"
        : "+f"(c[0]), "+f"(c[1]), "+f"(c[2]), "+f"(c[3])
        : "r"(a[0]), "r"(a[1]), "r"(a[2]), "r"(a[3]), "r"(b[0]), "r"(b[1]));
}

__device__ __forceinline__ u32 smem_u32(const void* p) {
    u32 a;
    asm("{ .reg .u64 t; cvta.to.shared.u64 t, %1; cvt.u32.u64 %0, t; }"
        : "=r"(a) : "l"(p));
    return a;
}

// ---------------------------------------------------------------------------
// Prep kernels
// ---------------------------------------------------------------------------
__global__ __launch_bounds__(256) void wprep_kernel(const float* __restrict__ W)
{
    int idx = blockIdx.x * 256 + threadIdx.x;
    if (idx >= 192 * CDIM) return;
    int n = idx >> 10, k = idx & 1023;
    float w = W[(size_t)k * 192 + n];
    __nv_bfloat16 hi = __float2bfloat16(w);
    g_wt_hi[(size_t)n * CDIM + k] = hi;
    g_wt_lo[(size_t)n * CDIM + k] = __float2bfloat16(w - __bfloat162float(hi));
}

__global__ __launch_bounds__(256) void xprep_kernel(const float* __restrict__ x)
{
    size_t i = ((size_t)blockIdx.x * 256 + threadIdx.x) * 4;
    float4 v = *reinterpret_cast<const float4*>(x + i);
    uint2 hv, lv;
    split2(v.x, v.y, hv.x, lv.x);
    split2(v.z, v.w, hv.y, lv.y);
    *reinterpret_cast<uint2*>(g_x_hi + i) = hv;
    *reinterpret_cast<uint2*>(g_x_lo + i) = lv;
}

// ---------------------------------------------------------------------------
// Kernel 1: QKV projection on HMMA (R7 core), epilogue emits split-bf16
// q (scaled), k, and transposed v.
// Grid (3, 128): bn 0=k, 1=q, 2=v. 256 thr = 8 warps (4M x 2N), BK=32.
// ---------------------------------------------------------------------------
#define XS_STR 34

__global__ __launch_bounds__(256) void qkv_mma_kernel(const float* __restrict__ bias)
{
    __shared__ __nv_bfloat16 xs_hi[128 * XS_STR];
    __shared__ __nv_bfloat16 xs_lo[128 * XS_STR];
    __shared__ __nv_bfloat16 ws_hi[64 * XS_STR];
    __shared__ __nv_bfloat16 ws_lo[64 * XS_STR];

    const int tid  = threadIdx.x;
    const int wid  = tid >> 5, lane = tid & 31;
    const int g    = lane >> 2, t = lane & 3;
    const int bn   = blockIdx.x;
    const int bm   = blockIdx.y;
    const int wm0  = (wid & 3) * 32;
    const int wn0  = (wid >> 2) * 32;

    const int rx  = tid >> 2;
    const int c8  = (tid & 3) * 8;
    const __nv_bfloat16* xh_src = g_x_hi + ((size_t)(bm * 128 + rx)) * CDIM + c8;
    const __nv_bfloat16* xl_src = g_x_lo + ((size_t)(bm * 128 + rx)) * CDIM + c8;
    const __nv_bfloat16* wh_src = g_wt_hi + ((size_t)(bn * 64 + rx)) * CDIM + c8;
    const __nv_bfloat16* wl_src = g_wt_lo + ((size_t)(bn * 64 + rx)) * CDIM + c8;

    const u32* xh32 = reinterpret_cast<const u32*>(xs_hi);
    const u32* xl32 = reinterpret_cast<const u32*>(xs_lo);
    const u32* wh32 = reinterpret_cast<const u32*>(ws_hi);
    const u32* wl32 = reinterpret_cast<const u32*>(ws_lo);

    float c[2][4][4];
#pragma unroll
    for (int i = 0; i < 2; i++)
#pragma unroll
        for (int j = 0; j < 4; j++)
#pragma unroll
            for (int q = 0; q < 4; q++) c[i][j][q] = 0.f;

    for (int st = 0; st < 32; st++) {
        const int k0 = st * 32;
        uint4 xh0 = *reinterpret_cast<const uint4*>(xh_src + k0);
        uint4 xh1 = *reinterpret_cast<const uint4*>(xh_src + (size_t)64 * CDIM + k0);
        uint4 xl0 = *reinterpret_cast<const uint4*>(xl_src + k0);
        uint4 xl1 = *reinterpret_cast<const uint4*>(xl_src + (size_t)64 * CDIM + k0);
        uint4 wh  = *reinterpret_cast<const uint4*>(wh_src + k0);
        uint4 wl  = *reinterpret_cast<const uint4*>(wl_src + k0);

        __syncthreads();
        {
            u32* d0 = (u32*)xs_hi + rx * 17 + (c8 >> 1);
            u32* d1 = (u32*)xs_hi + (rx + 64) * 17 + (c8 >> 1);
            d0[0] = xh0.x; d0[1] = xh0.y; d0[2] = xh0.z; d0[3] = xh0.w;
            d1[0] = xh1.x; d1[1] = xh1.y; d1[2] = xh1.z; d1[3] = xh1.w;
            u32* e0 = (u32*)xs_lo + rx * 17 + (c8 >> 1);
            u32* e1 = (u32*)xs_lo + (rx + 64) * 17 + (c8 >> 1);
            e0[0] = xl0.x; e0[1] = xl0.y; e0[2] = xl0.z; e0[3] = xl0.w;
            e1[0] = xl1.x; e1[1] = xl1.y; e1[2] = xl1.z; e1[3] = xl1.w;
            u32* f0 = (u32*)ws_hi + rx * 17 + (c8 >> 1);
            f0[0] = wh.x; f0[1] = wh.y; f0[2] = wh.z; f0[3] = wh.w;
            u32* f1 = (u32*)ws_lo + rx * 17 + (c8 >> 1);
            f1[0] = wl.x; f1[1] = wl.y; f1[2] = wl.z; f1[3] = wl.w;
        }
        __syncthreads();

#pragma unroll
        for (int ks = 0; ks < 2; ks++) {
            const int ko = ks * 8 + t;
            u32 ah[2][4], al[2][4];
#pragma unroll
            for (int i = 0; i < 2; i++) {
                const int rb = (wm0 + i * 16 + g) * 17 + ko;
                ah[i][0] = xh32[rb];
                ah[i][1] = xh32[rb + 8 * 17];
                ah[i][2] = xh32[rb + 4];
                ah[i][3] = xh32[rb + 8 * 17 + 4];
                al[i][0] = xl32[rb];
                al[i][1] = xl32[rb + 8 * 17];
                al[i][2] = xl32[rb + 4];
                al[i][3] = xl32[rb + 8 * 17 + 4];
            }
            u32 bh[4][2], bl[4][2];
#pragma unroll
            for (int j = 0; j < 4; j++) {
                const int nb = (wn0 + j * 8 + g) * 17 + ko;
                bh[j][0] = wh32[nb];
                bh[j][1] = wh32[nb + 4];
                bl[j][0] = wl32[nb];
                bl[j][1] = wl32[nb + 4];
            }
#pragma unroll
            for (int i = 0; i < 2; i++)
#pragma unroll
                for (int j = 0; j < 4; j++) {
                    mma16816(c[i][j], ah[i], bh[j]);
                    mma16816(c[i][j], al[i], bh[j]);
                    mma16816(c[i][j], ah[i], bl[j]);
                }
        }
    }

    // ---- epilogue: +bias, split to bf16 hi/lo, store (v transposed) ----
    const float* brow = bias + bn * 64;
    if (bn == 2) {
#pragma unroll
        for (int i = 0; i < 2; i++) {
            const int row0 = bm * 128 + wm0 + i * 16 + g;
            const int bidx = row0 >> 11;
            const int tt   = row0 & 2047;
#pragma unroll
            for (int j = 0; j < 4; j++) {
                const int col = wn0 + j * 8 + 2 * t;
                float2 bz = *reinterpret_cast<const float2*>(brow + col);
                float v00 = c[i][j][0] + bz.x, v01 = c[i][j][1] + bz.y;
                float v10 = c[i][j][2] + bz.x, v11 = c[i][j][3] + bz.y;
                size_t p0 = (size_t)(bidx * 64 + col) * 2048 + tt;
                size_t p1 = p0 + 2048;
                __nv_bfloat16 h;
                h = __float2bfloat16(v00); g_vth[p0] = h;
                g_vtl[p0] = __float2bfloat16(v00 - __bfloat162float(h));
                h = __float2bfloat16(v01); g_vth[p1] = h;
                g_vtl[p1] = __float2bfloat16(v01 - __bfloat162float(h));
                h = __float2bfloat16(v10); g_vth[p0 + 8] = h;
                g_vtl[p0 + 8] = __float2bfloat16(v10 - __bfloat162float(h));
                h = __float2bfloat16(v11); g_vth[p1 + 8] = h;
                g_vtl[p1 + 8] = __float2bfloat16(v11 - __bfloat162float(h));
            }
        }
    } else {
        __nv_bfloat16* dh = bn ? g_qh : g_kh;
        __nv_bfloat16* dl = bn ? g_ql : g_kl;
        const float sc = bn ? 0.125f : 1.0f;   // pre-scale q by 1/sqrt(64)
#pragma unroll
        for (int i = 0; i < 2; i++) {
            const int row0 = bm * 128 + wm0 + i * 16 + g;
#pragma unroll
            for (int j = 0; j < 4; j++) {
                const int col = wn0 + j * 8 + 2 * t;
                float2 bz = *reinterpret_cast<const float2*>(brow + col);
                float v00 = (c[i][j][0] + bz.x) * sc, v01 = (c[i][j][1] + bz.y) * sc;
                float v10 = (c[i][j][2] + bz.x) * sc, v11 = (c[i][j][3] + bz.y) * sc;
                u32 h0, l0, h1, l1;
                split2(v00, v01, h0, l0);
                split2(v10, v11, h1, l1);
                *reinterpret_cast<u32*>(dh + (size_t)row0 * HD + col) = h0;
                *reinterpret_cast<u32*>(dl + (size_t)row0 * HD + col) = l0;
                *reinterpret_cast<u32*>(dh + (size_t)(row0 + 8) * HD + col) = h1;
                *reinterpret_cast<u32*>(dl + (size_t)(row0 + 8) * HD + col) = l1;
            }
        }
    }
}

// ---------------------------------------------------------------------------
// Kernel 2: causal flash attention on HMMA, split bf16, register-passing P.
// CTA 128 thr / 4 warps; q-tile 64 rows (warp = 16 rows); key tile 64.
// Pairing (qt, 31-qt): grid (16, 8) = 128 CTAs x exactly 33 key tiles.
// cp.async double-buffered K/V tiles (72 KB dynamic smem).
// ---------------------------------------------------------------------------
#define KTW   36                 // u32 words per smem row (conflict-free)
#define PLANE (64 * KTW)         // 2304 words = 9216 B per operand plane
#define ATTN_SMEM (2 * 4 * PLANE * 4)   // 73728 B

__device__ __forceinline__ void cp_tile(u32 sbase, int buf, int t0, int tid,
    const __nv_bfloat16* kh_g, const __nv_bfloat16* kl_g,
    const __nv_bfloat16* vh_g, const __nv_bfloat16* vl_g)
{
    const u32 base = sbase + (u32)buf * 4 * PLANE * 4;
#pragma unroll
    for (int i = 0; i < 4; i++) {
        int id = i * 128 + tid;
        int row = id >> 3, ch = id & 7;
        u32 soff = (u32)(row * KTW + ch * 4) * 4;
        const void* s1 = kh_g + (size_t)(t0 + row) * HD + ch * 8;
        const void* s2 = kl_g + (size_t)(t0 + row) * HD + ch * 8;
        const void* s3 = vh_g + (size_t)row * TSEQ + t0 + ch * 8;
        const void* s4 = vl_g + (size_t)row * TSEQ + t0 + ch * 8;
        asm volatile("cp.async.ca.shared.global [%0], [%1], 16;"
                     :: "r"(base + 0 * PLANE * 4 + soff), "l"(s1) : "memory");
        asm volatile("cp.async.ca.shared.global [%0], [%1], 16;"
                     :: "r"(base + 1 * PLANE * 4 + soff), "l"(s2) : "memory");
        asm volatile("cp.async.ca.shared.global [%0], [%1], 16;"
                     :: "r"(base + 2 * PLANE * 4 + soff), "l"(s3) : "memory");
        asm volatile("cp.async.ca.shared.global [%0], [%1], 16;"
                     :: "r"(base + 3 * PLANE * 4 + soff), "l"(s4) : "memory");
    }
    asm volatile("cp.async.commit_group;" ::: "memory");
}

__global__ __launch_bounds__(128) void attn_hmma_kernel(float* __restrict__ out)
{
    extern __shared__ u32 smem_dyn[];
    const u32 sbase = smem_u32(smem_dyn);

    const int tid = threadIdx.x;
    const int w = tid >> 5, lane = tid & 31;
    const int g = lane >> 2, t = lane & 3;
    const int bb = blockIdx.y, bx = blockIdx.x;

    const __nv_bfloat16* qh_g = g_qh + (size_t)bb * TSEQ * HD;
    const __nv_bfloat16* ql_g = g_ql + (size_t)bb * TSEQ * HD;
    const __nv_bfloat16* kh_g = g_kh + (size_t)bb * TSEQ * HD;
    const __nv_bfloat16* kl_g = g_kl + (size_t)bb * TSEQ * HD;
    const __nv_bfloat16* vh_g = g_vth + (size_t)bb * HD * TSEQ;
    const __nv_bfloat16* vl_g = g_vtl + (size_t)bb * HD * TSEQ;

    for (int half = 0; half < 2; half++) {
        const int qt = half ? 31 - bx : bx;
        const int qrow0 = qt * 64;
        const int r0 = w * 16 + g;

        // Q fragments (A operand), hi and lo
        u32 qh[4][4], ql[4][4];
#pragma unroll
        for (int kk = 0; kk < 4; kk++) {
            const size_t b0 = (size_t)(qrow0 + r0) * HD + kk * 16 + 2 * t;
            const size_t b1 = b0 + 8 * HD;
            qh[kk][0] = *(const u32*)(qh_g + b0);
            qh[kk][1] = *(const u32*)(qh_g + b1);
            qh[kk][2] = *(const u32*)(qh_g + b0 + 8);
            qh[kk][3] = *(const u32*)(qh_g + b1 + 8);
            ql[kk][0] = *(const u32*)(ql_g + b0);
            ql[kk][1] = *(const u32*)(ql_g + b1);
            ql[kk][2] = *(const u32*)(ql_g + b0 + 8);
            ql[kk][3] = *(const u32*)(ql_g + b1 + 8);
        }

        float o[8][4];
#pragma unroll
        for (int nt = 0; nt < 8; nt++)
#pragma unroll
            for (int q = 0; q < 4; q++) o[nt][q] = 0.f;
        float m0 = -1e30f, m1 = -1e30f, l0 = 0.f, l1 = 0.f;

        cp_tile(sbase, 0, 0, tid, kh_g, kl_g, vh_g, vl_g);

        for (int kt = 0; kt <= qt; kt++) {
            if (kt < qt) {
                cp_tile(sbase, (kt + 1) & 1, (kt + 1) * 64, tid, kh_g, kl_g, vh_g, vl_g);
                asm volatile("cp.async.wait_group 1;" ::: "memory");
            } else {
                asm volatile("cp.async.wait_group 0;" ::: "memory");
            }
            __syncthreads();

            const u32* kh_s = smem_dyn + ((kt & 1) * 4 + 0) * PLANE;
            const u32* kl_s = smem_dyn + ((kt & 1) * 4 + 1) * PLANE;
            const u32* vh_s = smem_dyn + ((kt & 1) * 4 + 2) * PLANE;
            const u32* vl_s = smem_dyn + ((kt & 1) * 4 + 3) * PLANE;

            // ---- GEMM1: S = Q @ K^T (3-product split) ----
            float s[8][4];
#pragma unroll
            for (int nt = 0; nt < 8; nt++)
#pragma unroll
                for (int q = 0; q < 4; q++) s[nt][q] = 0.f;
#pragma unroll
            for (int kk = 0; kk < 4; kk++) {
#pragma unroll
                for (int nt = 0; nt < 8; nt++) {
                    const int bi = (nt * 8 + g) * KTW + kk * 8 + t;
                    u32 bh[2] = { kh_s[bi], kh_s[bi + 4] };
                    u32 bl[2] = { kl_s[bi], kl_s[bi + 4] };
                    mma16816(s[nt], qh[kk], bh);
                    mma16816(s[nt], ql[kk], bh);
                    mma16816(s[nt], qh[kk], bl);
                }
            }

            // ---- causal mask (diagonal tile only) ----
            if (kt == qt) {
                const int rg = qrow0 + r0;
#pragma unroll
                for (int nt = 0; nt < 8; nt++) {
                    const int col = qrow0 + nt * 8 + 2 * t;   // t0 == qrow0 here
                    if (col     > rg)     s[nt][0] = -1e30f;
                    if (col + 1 > rg)     s[nt][1] = -1e30f;
                    if (col     > rg + 8) s[nt][2] = -1e30f;
                    if (col + 1 > rg + 8) s[nt][3] = -1e30f;
                }
            }

            // ---- streaming softmax (2 rows per thread) ----
            float mx0 = -1e30f, mx1 = -1e30f;
#pragma unroll
            for (int nt = 0; nt < 8; nt++) {
                mx0 = fmaxf(mx0, fmaxf(s[nt][0], s[nt][1]));
                mx1 = fmaxf(mx1, fmaxf(s[nt][2], s[nt][3]));
            }
            mx0 = fmaxf(mx0, __shfl_xor_sync(0xffffffffu, mx0, 1));
            mx0 = fmaxf(mx0, __shfl_xor_sync(0xffffffffu, mx0, 2));
            mx1 = fmaxf(mx1, __shfl_xor_sync(0xffffffffu, mx1, 1));
            mx1 = fmaxf(mx1, __shfl_xor_sync(0xffffffffu, mx1, 2));
            const float mn0 = fmaxf(m0, mx0), mn1 = fmaxf(m1, mx1);
            const float c0r = __expf(m0 - mn0), c1r = __expf(m1 - mn1);
            m0 = mn0; m1 = mn1;

            float s0 = 0.f, s1 = 0.f;
            u32 ph[4][4], pl[4][4];
#pragma unroll
            for (int q2 = 0; q2 < 4; q2++) {
                float p00 = __expf(s[2*q2][0]   - mn0), p01 = __expf(s[2*q2][1]   - mn0);
                float p02 = __expf(s[2*q2][2]   - mn1), p03 = __expf(s[2*q2][3]   - mn1);
                float p10 = __expf(s[2*q2+1][0] - mn0), p11 = __expf(s[2*q2+1][1] - mn0);
                float p12 = __expf(s[2*q2+1][2] - mn1), p13 = __expf(s[2*q2+1][3] - mn1);
                s0 += (p00 + p01) + (p10 + p11);
                s1 += (p02 + p03) + (p12 + p13);
                split2(p00, p01, ph[q2][0], pl[q2][0]);
                split2(p02, p03, ph[q2][1], pl[q2][1]);
                split2(p10, p11, ph[q2][2], pl[q2][2]);
                split2(p12, p13, ph[q2][3], pl[q2][3]);
            }
            s0 += __shfl_xor_sync(0xffffffffu, s0, 1);
            s0 += __shfl_xor_sync(0xffffffffu, s0, 2);
            s1 += __shfl_xor_sync(0xffffffffu, s1, 1);
            s1 += __shfl_xor_sync(0xffffffffu, s1, 2);
            l0 = l0 * c0r + s0;
            l1 = l1 * c1r + s1;

#pragma unroll
            for (int nt = 0; nt < 8; nt++) {
                o[nt][0] *= c0r; o[nt][1] *= c0r;
                o[nt][2] *= c1r; o[nt][3] *= c1r;
            }

            // ---- GEMM2: O += P @ V (3-product split; P stays in registers) ----
#pragma unroll
            for (int kk = 0; kk < 4; kk++) {
#pragma unroll
                for (int nt = 0; nt < 8; nt++) {
                    const int bi = (nt * 8 + g) * KTW + kk * 8 + t;
                    u32 bh[2] = { vh_s[bi], vh_s[bi + 4] };
                    u32 bl[2] = { vl_s[bi], vl_s[bi + 4] };
                    mma16816(o[nt], ph[kk], bh);
                    mma16816(o[nt], pl[kk], bh);
                    mma16816(o[nt], ph[kk], bl);
                }
            }
            __syncthreads();   // readers done before next tile's cp.async overwrite
        }

        // ---- finalize ----
        const float inv0 = 1.f / l0, inv1 = 1.f / l1;
        float* orow0 = out + ((size_t)bb * TSEQ + qrow0 + r0) * HD;
        float* orow1 = orow0 + 8 * HD;
#pragma unroll
        for (int nt = 0; nt < 8; nt++) {
            float2 a, b2;
            a.x  = o[nt][0] * inv0; a.y  = o[nt][1] * inv0;
            b2.x = o[nt][2] * inv1; b2.y = o[nt][3] * inv1;
            *reinterpret_cast<float2*>(orow0 + nt * 8 + 2 * t) = a;
            *reinterpret_cast<float2*>(orow1 + nt * 8 + 2 * t) = b2;
        }
    }
}

// ---------------------------------------------------------------------------
extern "C" void kernel_launch(void* const* d_in, const int* in_sizes, int n_in,
                              void* d_out, int out_size)
{
    const float* x = (const float*)d_in[0];
    const float* W = (const float*)d_in[1];
    const float* b = (const float*)d_in[2];
    float* out = (float*)d_out;

    (void)in_sizes; (void)n_in; (void)out_size;

    static int attr_set = 0;
    if (!attr_set) {
        cudaFuncSetAttribute(attn_hmma_kernel,
                             cudaFuncAttributeMaxDynamicSharedMemorySize, ATTN_SMEM);
        attr_set = 1;
    }

    wprep_kernel<<<(192 * CDIM + 255) / 256, 256>>>(W);
    xprep_kernel<<<(BSZ * TSEQ * CDIM) / (4 * 256), 256>>>(x);
    qkv_mma_kernel<<<dim3(3, 128), 256>>>(b);

    dim3 g2(16, BSZ);
    attn_hmma_kernel<<<g2, 128, ATTN_SMEM>>>(out);
}

// round 9
// speedup vs baseline: 3.2117x; 1.2953x over previous
#include <cuda_runtime.h>
#include <cuda_bf16.h>
#include <math.h>
#include <stdint.h>

#define BSZ   8
#define TSEQ  2048
#define CDIM  1024
#define HD    64

typedef unsigned int u32;

// split-bf16 W transposed ([192][1024])
__device__ __align__(16) __nv_bfloat16 g_wt_hi[192 * CDIM];
__device__ __align__(16) __nv_bfloat16 g_wt_lo[192 * CDIM];

// split-bf16 attention operands (written by qkv kernel)
__device__ __align__(16) __nv_bfloat16 g_qh[BSZ * TSEQ * HD];  // pre-scaled 0.125
__device__ __align__(16) __nv_bfloat16 g_ql[BSZ * TSEQ * HD];
__device__ __align__(16) __nv_bfloat16 g_kh[BSZ * TSEQ * HD];
__device__ __align__(16) __nv_bfloat16 g_kl[BSZ * TSEQ * HD];
__device__ __align__(16) __nv_bfloat16 g_vth[BSZ * HD * TSEQ]; // [b][d][t]
__device__ __align__(16) __nv_bfloat16 g_vtl[BSZ * HD * TSEQ];

__device__ __forceinline__ u32 bf2(float lo, float hi) {
    u32 r; asm("cvt.rn.bf16x2.f32 %0, %1, %2;" : "=r"(r) : "f"(hi), "f"(lo));
    return r;
}
__device__ __forceinline__ void split2(float a, float b, u32& hi, u32& lo) {
    hi = bf2(a, b);
    float ha = __uint_as_float(hi << 16);
    float hb = __uint_as_float(hi & 0xffff0000u);
    lo = bf2(a - ha, b - hb);
}
__device__ __forceinline__ void mma16816(float c[4], const u32 a[4], const u32 b[2]) {
    asm volatile(
        "mma.sync.aligned.m16n8k16.row.col.f32.bf16.bf16.f32 "
        "{%0,%1,%2,%3}, {%4,%5,%6,%7}, {%8,%9}, {%0,%1,%2,%3};"
        : "+f"(c[0]), "+f"(c[1]), "+f"(c[2]), "+f"(c[3])
        : "r"(a[0]), "r"(a[1]), "r"(a[2]), "r"(a[3]), "r"(b[0]), "r"(b[1]));
}
__device__ __forceinline__ u32 smem_u32(const void* p) {
    u32 a;
    asm("{ .reg .u64 t; cvta.to.shared.u64 t, %1; cvt.u32.u64 %0, t; }"
        : "=r"(a) : "l"(p));
    return a;
}

// ---------------------------------------------------------------------------
// Kernel 0: prep split-bf16 transposed weights (tiny).
// ---------------------------------------------------------------------------
__global__ __launch_bounds__(256) void wprep_kernel(const float* __restrict__ W)
{
    int idx = blockIdx.x * 256 + threadIdx.x;
    if (idx >= 192 * CDIM) return;
    int n = idx >> 10, k = idx & 1023;
    float w = W[(size_t)k * 192 + n];
    __nv_bfloat16 hi = __float2bfloat16(w);
    g_wt_hi[(size_t)n * CDIM + k] = hi;
    g_wt_lo[(size_t)n * CDIM + k] = __float2bfloat16(w - __bfloat162float(hi));
}

// ---------------------------------------------------------------------------
// Kernel 1: QKV projection, single wave.  BM=128, BN=192, BK=32, grid 128.
// fp32 x converted to split-bf16 in-kernel (no scratch round trip).
// 8 warps = 4M x 2N; warp tile 32 x 96 (2 M-atoms x 12 N-atoms).
// Epilogue emits split-bf16 q(scaled)/k and transposed v.
// ---------------------------------------------------------------------------
__global__ __launch_bounds__(256) void qkv_mma_kernel(
    const float* __restrict__ x, const float* __restrict__ bias)
{
    __shared__ u32 xs_hi[128 * 17];
    __shared__ u32 xs_lo[128 * 17];
    __shared__ u32 ws_hi[192 * 17];
    __shared__ u32 ws_lo[192 * 17];

    const int tid  = threadIdx.x;
    const int wid  = tid >> 5, lane = tid & 31;
    const int g    = lane >> 2, t = lane & 3;
    const int bm   = blockIdx.x;
    const int wm0  = (wid & 3) * 32;
    const int wn0  = (wid >> 2) * 96;

    // x loader: row = tid>>1 (0..127), 16 floats at (tid&1)*16
    const int xrow = tid >> 1;
    const int xfc  = (tid & 1) * 16;
    const float* xsrc = x + ((size_t)(bm * 128 + xrow)) * CDIM + xfc;

    float c[2][12][4];
#pragma unroll
    for (int i = 0; i < 2; i++)
#pragma unroll
        for (int j = 0; j < 12; j++)
#pragma unroll
            for (int q = 0; q < 4; q++) c[i][j][q] = 0.f;

    for (int st = 0; st < 32; st++) {
        const int k0 = st * 32;
        // hoisted gmem loads
        float4 xv[4];
#pragma unroll
        for (int q = 0; q < 4; q++)
            xv[q] = *reinterpret_cast<const float4*>(xsrc + k0 + q * 4);
        uint4 wreg[6];
#pragma unroll
        for (int i = 0; i < 3; i++) {
            int idx = i * 256 + tid;          // 0..767
            int n = idx >> 2, ch = idx & 3;
            wreg[i]     = *reinterpret_cast<const uint4*>(g_wt_hi + (size_t)n * CDIM + k0 + ch * 8);
            wreg[i + 3] = *reinterpret_cast<const uint4*>(g_wt_lo + (size_t)n * CDIM + k0 + ch * 8);
        }

        __syncthreads();
        {
            u32* dh = xs_hi + xrow * 17 + (xfc >> 1);
            u32* dl = xs_lo + xrow * 17 + (xfc >> 1);
#pragma unroll
            for (int q = 0; q < 4; q++) {
                u32 h0, l0, h1, l1;
                split2(xv[q].x, xv[q].y, h0, l0);
                split2(xv[q].z, xv[q].w, h1, l1);
                dh[q * 2] = h0; dh[q * 2 + 1] = h1;
                dl[q * 2] = l0; dl[q * 2 + 1] = l1;
            }
#pragma unroll
            for (int i = 0; i < 3; i++) {
                int idx = i * 256 + tid;
                int n = idx >> 2, ch = idx & 3;
                u32* wh = ws_hi + n * 17 + ch * 4;
                u32* wl = ws_lo + n * 17 + ch * 4;
                wh[0] = wreg[i].x; wh[1] = wreg[i].y; wh[2] = wreg[i].z; wh[3] = wreg[i].w;
                wl[0] = wreg[i+3].x; wl[1] = wreg[i+3].y; wl[2] = wreg[i+3].z; wl[3] = wreg[i+3].w;
            }
        }
        __syncthreads();

#pragma unroll
        for (int ks = 0; ks < 2; ks++) {
            const int ko = ks * 8 + t;
            u32 ah[2][4], al[2][4];
#pragma unroll
            for (int i = 0; i < 2; i++) {
                const int rb = (wm0 + i * 16 + g) * 17 + ko;
                ah[i][0] = xs_hi[rb];
                ah[i][1] = xs_hi[rb + 8 * 17];
                ah[i][2] = xs_hi[rb + 4];
                ah[i][3] = xs_hi[rb + 8 * 17 + 4];
                al[i][0] = xs_lo[rb];
                al[i][1] = xs_lo[rb + 8 * 17];
                al[i][2] = xs_lo[rb + 4];
                al[i][3] = xs_lo[rb + 8 * 17 + 4];
            }
#pragma unroll
            for (int j = 0; j < 12; j++) {
                const int nb = (wn0 + j * 8 + g) * 17 + ko;
                u32 bh[2] = { ws_hi[nb], ws_hi[nb + 4] };
                u32 bl[2] = { ws_lo[nb], ws_lo[nb + 4] };
#pragma unroll
                for (int i = 0; i < 2; i++) {
                    mma16816(c[i][j], ah[i], bh);
                    mma16816(c[i][j], al[i], bh);
                    mma16816(c[i][j], ah[i], bl);
                }
            }
        }
    }

    // ---- epilogue ----
#pragma unroll
    for (int i = 0; i < 2; i++) {
        const int row0 = bm * 128 + wm0 + i * 16 + g;
#pragma unroll
        for (int j = 0; j < 12; j++) {
            const int colg = wn0 + j * 8 + 2 * t;
            const int blk  = colg >> 6;          // 0=k, 1=q, 2=v
            const int col  = colg & 63;
            const float bz0 = bias[colg], bz1 = bias[colg + 1];
            float v00 = c[i][j][0] + bz0, v01 = c[i][j][1] + bz1;
            float v10 = c[i][j][2] + bz0, v11 = c[i][j][3] + bz1;
            if (blk == 2) {
                const int bidx = row0 >> 11;
                const int tt   = row0 & 2047;
                size_t p0 = (size_t)(bidx * 64 + col) * 2048 + tt;
                size_t p1 = p0 + 2048;
                __nv_bfloat16 h;
                h = __float2bfloat16(v00); g_vth[p0] = h;
                g_vtl[p0] = __float2bfloat16(v00 - __bfloat162float(h));
                h = __float2bfloat16(v01); g_vth[p1] = h;
                g_vtl[p1] = __float2bfloat16(v01 - __bfloat162float(h));
                h = __float2bfloat16(v10); g_vth[p0 + 8] = h;
                g_vtl[p0 + 8] = __float2bfloat16(v10 - __bfloat162float(h));
                h = __float2bfloat16(v11); g_vth[p1 + 8] = h;
                g_vtl[p1 + 8] = __float2bfloat16(v11 - __bfloat162float(h));
            } else {
                __nv_bfloat16* dh = blk ? g_qh : g_kh;
                __nv_bfloat16* dl = blk ? g_ql : g_kl;
                const float sc = blk ? 0.125f : 1.0f;
                v00 *= sc; v01 *= sc; v10 *= sc; v11 *= sc;
                u32 h0, l0, h1, l1;
                split2(v00, v01, h0, l0);
                split2(v10, v11, h1, l1);
                *reinterpret_cast<u32*>(dh + (size_t)row0 * HD + col) = h0;
                *reinterpret_cast<u32*>(dl + (size_t)row0 * HD + col) = l0;
                *reinterpret_cast<u32*>(dh + (size_t)(row0 + 8) * HD + col) = h1;
                *reinterpret_cast<u32*>(dl + (size_t)(row0 + 8) * HD + col) = l1;
            }
        }
    }
}

// ---------------------------------------------------------------------------
// Kernel 2: causal flash attention on HMMA, dual warp-group split-K.
// 256 thr = 2 groups of 4 warps; group gp handles key tiles kt == gp (mod 2)
// with private double-buffered smem + private (m,l,O); merged at the end.
// Pairing (qt, 31-qt): grid (16,8) = 128 CTAs, balanced.
// ---------------------------------------------------------------------------
#define KTW   36
#define PLANE (64 * KTW)                 // words per operand plane
#define BUF_WORDS (4 * PLANE)            // one buffer: 4 planes
#define GRP_WORDS (2 * BUF_WORDS)        // double buffered
#define MERGE_OFF (2 * GRP_WORDS)
#define MO_STR 66
#define ATTN_SMEM ((MERGE_OFF + 64 * MO_STR + 128) * 4)

__device__ __forceinline__ void barg(int id) {
    asm volatile("bar.sync %0, 128;" :: "r"(id) : "memory");
}

__device__ __forceinline__ void cp_tile(u32 base_bytes, int t0, int ltid,
    const __nv_bfloat16* kh_g, const __nv_bfloat16* kl_g,
    const __nv_bfloat16* vh_g, const __nv_bfloat16* vl_g)
{
#pragma unroll
    for (int i = 0; i < 4; i++) {
        int id = i * 128 + ltid;
        int row = id >> 3, ch = id & 7;
        u32 soff = (u32)(row * KTW + ch * 4) * 4;
        const void* s1 = kh_g + (size_t)(t0 + row) * HD + ch * 8;
        const void* s2 = kl_g + (size_t)(t0 + row) * HD + ch * 8;
        const void* s3 = vh_g + (size_t)row * TSEQ + t0 + ch * 8;
        const void* s4 = vl_g + (size_t)row * TSEQ + t0 + ch * 8;
        asm volatile("cp.async.ca.shared.global [%0], [%1], 16;"
                     :: "r"(base_bytes + 0 * PLANE * 4 + soff), "l"(s1) : "memory");
        asm volatile("cp.async.ca.shared.global [%0], [%1], 16;"
                     :: "r"(base_bytes + 1 * PLANE * 4 + soff), "l"(s2) : "memory");
        asm volatile("cp.async.ca.shared.global [%0], [%1], 16;"
                     :: "r"(base_bytes + 2 * PLANE * 4 + soff), "l"(s3) : "memory");
        asm volatile("cp.async.ca.shared.global [%0], [%1], 16;"
                     :: "r"(base_bytes + 3 * PLANE * 4 + soff), "l"(s4) : "memory");
    }
    asm volatile("cp.async.commit_group;" ::: "memory");
}

__global__ __launch_bounds__(256) void attn_hmma_kernel(float* __restrict__ out)
{
    extern __shared__ u32 smem_dyn[];
    const u32 sbase = smem_u32(smem_dyn);

    const int tid = threadIdx.x;
    const int w = tid >> 5, lane = tid & 31;
    const int gp = w >> 2;              // warp group 0/1
    const int wg = w & 3;
    const int g = lane >> 2, t = lane & 3;
    const int ltid = tid & 127;
    const int bb = blockIdx.y, bx = blockIdx.x;

    const __nv_bfloat16* qh_g = g_qh + (size_t)bb * TSEQ * HD;
    const __nv_bfloat16* ql_g = g_ql + (size_t)bb * TSEQ * HD;
    const __nv_bfloat16* kh_g = g_kh + (size_t)bb * TSEQ * HD;
    const __nv_bfloat16* kl_g = g_kl + (size_t)bb * TSEQ * HD;
    const __nv_bfloat16* vh_g = g_vth + (size_t)bb * HD * TSEQ;
    const __nv_bfloat16* vl_g = g_vtl + (size_t)bb * HD * TSEQ;

    const u32 gbase = sbase + (u32)gp * GRP_WORDS * 4;
    float* mo  = (float*)(smem_dyn + MERGE_OFF);
    float* mmv = mo + 64 * MO_STR;
    float* mlv = mmv + 64;

    for (int half = 0; half < 2; half++) {
        const int qt = half ? 31 - bx : bx;
        const int qrow0 = qt * 64;
        const int r0 = wg * 16 + g;      // local row within 64-row q tile

        // Q fragments (A operand)
        u32 qh[4][4], ql[4][4];
#pragma unroll
        for (int kk = 0; kk < 4; kk++) {
            const size_t b0 = (size_t)(qrow0 + r0) * HD + kk * 16 + 2 * t;
            const size_t b1 = b0 + 8 * HD;
            qh[kk][0] = *(const u32*)(qh_g + b0);
            qh[kk][1] = *(const u32*)(qh_g + b1);
            qh[kk][2] = *(const u32*)(qh_g + b0 + 8);
            qh[kk][3] = *(const u32*)(qh_g + b1 + 8);
            ql[kk][0] = *(const u32*)(ql_g + b0);
            ql[kk][1] = *(const u32*)(ql_g + b1);
            ql[kk][2] = *(const u32*)(ql_g + b0 + 8);
            ql[kk][3] = *(const u32*)(ql_g + b1 + 8);
        }

        float o[8][4];
#pragma unroll
        for (int nt = 0; nt < 8; nt++)
#pragma unroll
            for (int q = 0; q < 4; q++) o[nt][q] = 0.f;
        float m0 = -1e30f, m1 = -1e30f, l0 = 0.f, l1 = 0.f;

        const int n_t = (qt >= gp) ? ((qt - gp) >> 1) + 1 : 0;
        if (n_t > 0) cp_tile(gbase, gp * 64, ltid, kh_g, kl_g, vh_g, vl_g);

        for (int i = 0; i < n_t; i++) {
            const int kt = gp + 2 * i;
            const int t0 = kt * 64;
            if (i + 1 < n_t) {
                cp_tile(gbase + (u32)((i + 1) & 1) * BUF_WORDS * 4,
                        (gp + 2 * (i + 1)) * 64, ltid, kh_g, kl_g, vh_g, vl_g);
                asm volatile("cp.async.wait_group 1;" ::: "memory");
            } else {
                asm volatile("cp.async.wait_group 0;" ::: "memory");
            }
            barg(1 + gp);

            const u32* buf = smem_dyn + gp * GRP_WORDS + (u32)(i & 1) * BUF_WORDS;
            const u32* kh_s = buf;
            const u32* kl_s = buf + PLANE;
            const u32* vh_s = buf + 2 * PLANE;
            const u32* vl_s = buf + 3 * PLANE;

            // ---- GEMM1: S = Q @ K^T ----
            float s[8][4];
#pragma unroll
            for (int nt = 0; nt < 8; nt++)
#pragma unroll
                for (int q = 0; q < 4; q++) s[nt][q] = 0.f;
#pragma unroll
            for (int kk = 0; kk < 4; kk++) {
#pragma unroll
                for (int nt = 0; nt < 8; nt++) {
                    const int bi = (nt * 8 + g) * KTW + kk * 8 + t;
                    u32 bh[2] = { kh_s[bi], kh_s[bi + 4] };
                    u32 bl[2] = { kl_s[bi], kl_s[bi + 4] };
                    mma16816(s[nt], qh[kk], bh);
                    mma16816(s[nt], ql[kk], bh);
                    mma16816(s[nt], qh[kk], bl);
                }
            }

            if (kt == qt) {   // diagonal tile: causal mask
                const int rg = qrow0 + r0;
#pragma unroll
                for (int nt = 0; nt < 8; nt++) {
                    const int col = t0 + nt * 8 + 2 * t;
                    if (col     > rg)     s[nt][0] = -1e30f;
                    if (col + 1 > rg)     s[nt][1] = -1e30f;
                    if (col     > rg + 8) s[nt][2] = -1e30f;
                    if (col + 1 > rg + 8) s[nt][3] = -1e30f;
                }
            }

            // ---- streaming softmax ----
            float mx0 = -1e30f, mx1 = -1e30f;
#pragma unroll
            for (int nt = 0; nt < 8; nt++) {
                mx0 = fmaxf(mx0, fmaxf(s[nt][0], s[nt][1]));
                mx1 = fmaxf(mx1, fmaxf(s[nt][2], s[nt][3]));
            }
            mx0 = fmaxf(mx0, __shfl_xor_sync(0xffffffffu, mx0, 1));
            mx0 = fmaxf(mx0, __shfl_xor_sync(0xffffffffu, mx0, 2));
            mx1 = fmaxf(mx1, __shfl_xor_sync(0xffffffffu, mx1, 1));
            mx1 = fmaxf(mx1, __shfl_xor_sync(0xffffffffu, mx1, 2));
            const float mn0 = fmaxf(m0, mx0), mn1 = fmaxf(m1, mx1);
            const float c0r = __expf(m0 - mn0), c1r = __expf(m1 - mn1);
            m0 = mn0; m1 = mn1;

            float s0 = 0.f, s1 = 0.f;
            u32 ph[4][4], pl[4][4];
#pragma unroll
            for (int q2 = 0; q2 < 4; q2++) {
                float p00 = __expf(s[2*q2][0]   - mn0), p01 = __expf(s[2*q2][1]   - mn0);
                float p02 = __expf(s[2*q2][2]   - mn1), p03 = __expf(s[2*q2][3]   - mn1);
                float p10 = __expf(s[2*q2+1][0] - mn0), p11 = __expf(s[2*q2+1][1] - mn0);
                float p12 = __expf(s[2*q2+1][2] - mn1), p13 = __expf(s[2*q2+1][3] - mn1);
                s0 += (p00 + p01) + (p10 + p11);
                s1 += (p02 + p03) + (p12 + p13);
                split2(p00, p01, ph[q2][0], pl[q2][0]);
                split2(p02, p03, ph[q2][1], pl[q2][1]);
                split2(p10, p11, ph[q2][2], pl[q2][2]);
                split2(p12, p13, ph[q2][3], pl[q2][3]);
            }
            s0 += __shfl_xor_sync(0xffffffffu, s0, 1);
            s0 += __shfl_xor_sync(0xffffffffu, s0, 2);
            s1 += __shfl_xor_sync(0xffffffffu, s1, 1);
            s1 += __shfl_xor_sync(0xffffffffu, s1, 2);
            l0 = l0 * c0r + s0;
            l1 = l1 * c1r + s1;

#pragma unroll
            for (int nt = 0; nt < 8; nt++) {
                o[nt][0] *= c0r; o[nt][1] *= c0r;
                o[nt][2] *= c1r; o[nt][3] *= c1r;
            }

            // ---- GEMM2: O += P @ V ----
#pragma unroll
            for (int kk = 0; kk < 4; kk++) {
#pragma unroll
                for (int nt = 0; nt < 8; nt++) {
                    const int bi = (nt * 8 + g) * KTW + kk * 8 + t;
                    u32 bh[2] = { vh_s[bi], vh_s[bi + 4] };
                    u32 bl[2] = { vl_s[bi], vl_s[bi + 4] };
                    mma16816(o[nt], ph[kk], bh);
                    mma16816(o[nt], pl[kk], bh);
                    mma16816(o[nt], ph[kk], bl);
                }
            }
            barg(1 + gp);
        }

        // ---- merge the two groups ----
        __syncthreads();
        if (gp == 1) {
            const int ra = r0, rb = r0 + 8;
#pragma unroll
            for (int nt = 0; nt < 8; nt++) {
                const int cc = nt * 8 + 2 * t;
                mo[ra * MO_STR + cc]     = o[nt][0];
                mo[ra * MO_STR + cc + 1] = o[nt][1];
                mo[rb * MO_STR + cc]     = o[nt][2];
                mo[rb * MO_STR + cc + 1] = o[nt][3];
            }
            if (t == 0) {
                mmv[ra] = m0; mlv[ra] = l0;
                mmv[rb] = m1; mlv[rb] = l1;
            }
        }
        __syncthreads();
        if (gp == 0) {
            const int ra = r0, rb = r0 + 8;
            const float mA = mmv[ra], lA = mlv[ra];
            const float mB = mmv[rb], lB = mlv[rb];
            const float mnA = fmaxf(m0, mA), mnB = fmaxf(m1, mB);
            const float f0A = __expf(m0 - mnA), f1A = __expf(mA - mnA);
            const float f0B = __expf(m1 - mnB), f1B = __expf(mB - mnB);
            const float invA = 1.f / (l0 * f0A + lA * f1A);
            const float invB = 1.f / (l1 * f0B + lB * f1B);
            float* orow0 = out + ((size_t)bb * TSEQ + qrow0 + ra) * HD;
            float* orow1 = out + ((size_t)bb * TSEQ + qrow0 + rb) * HD;
#pragma unroll
            for (int nt = 0; nt < 8; nt++) {
                const int cc = nt * 8 + 2 * t;
                float2 oa, ob;
                oa.x = (o[nt][0] * f0A + mo[ra * MO_STR + cc]     * f1A) * invA;
                oa.y = (o[nt][1] * f0A + mo[ra * MO_STR + cc + 1] * f1A) * invA;
                ob.x = (o[nt][2] * f0B + mo[rb * MO_STR + cc]     * f1B) * invB;
                ob.y = (o[nt][3] * f0B + mo[rb * MO_STR + cc + 1] * f1B) * invB;
                *reinterpret_cast<float2*>(orow0 + cc) = oa;
                *reinterpret_cast<float2*>(orow1 + cc) = ob;
            }
        }
        __syncthreads();   // merge region free before next half
    }
}

// ---------------------------------------------------------------------------
extern "C" void kernel_launch(void* const* d_in, const int* in_sizes, int n_in,
                              void* d_out, int out_size)
{
    const float* x = (const float*)d_in[0];
    const float* W = (const float*)d_in[1];
    const float* b = (const float*)d_in[2];
    float* out = (float*)d_out;

    (void)in_sizes; (void)n_in; (void)out_size;

    static int attr_set = 0;
    if (!attr_set) {
        cudaFuncSetAttribute(attn_hmma_kernel,
                             cudaFuncAttributeMaxDynamicSharedMemorySize, ATTN_SMEM);
        attr_set = 1;
    }

    wprep_kernel<<<(192 * CDIM + 255) / 256, 256>>>(W);
    qkv_mma_kernel<<<128, 256>>>(x, b);

    dim3 g2(16, BSZ);
    attn_hmma_kernel<<<g2, 256, ATTN_SMEM>>>(out);
}

// round 10
// speedup vs baseline: 3.3357x; 1.0386x over previous
#include <cuda_runtime.h>
#include <cuda_bf16.h>
#include <math.h>
#include <stdint.h>

#define BSZ   8
#define TSEQ  2048
#define CDIM  1024
#define HD    64

typedef unsigned int u32;

// split-bf16 W transposed ([192][1024])
__device__ __align__(16) __nv_bfloat16 g_wt_hi[192 * CDIM];
__device__ __align__(16) __nv_bfloat16 g_wt_lo[192 * CDIM];

// split-bf16 attention operands (written by qkv kernel)
__device__ __align__(16) __nv_bfloat16 g_qh[BSZ * TSEQ * HD];  // pre-scaled 0.125
__device__ __align__(16) __nv_bfloat16 g_ql[BSZ * TSEQ * HD];
__device__ __align__(16) __nv_bfloat16 g_kh[BSZ * TSEQ * HD];
__device__ __align__(16) __nv_bfloat16 g_kl[BSZ * TSEQ * HD];
__device__ __align__(16) __nv_bfloat16 g_vth[BSZ * HD * TSEQ]; // [b][d][t]
__device__ __align__(16) __nv_bfloat16 g_vtl[BSZ * HD * TSEQ];

__device__ __forceinline__ u32 bf2(float lo, float hi) {
    u32 r; asm("cvt.rn.bf16x2.f32 %0, %1, %2;" : "=r"(r) : "f"(hi), "f"(lo));
    return r;
}
__device__ __forceinline__ void split2(float a, float b, u32& hi, u32& lo) {
    hi = bf2(a, b);
    float ha = __uint_as_float(hi << 16);
    float hb = __uint_as_float(hi & 0xffff0000u);
    lo = bf2(a - ha, b - hb);
}
__device__ __forceinline__ void mma16816(float c[4], const u32 a[4], const u32 b[2]) {
    asm volatile(
        "mma.sync.aligned.m16n8k16.row.col.f32.bf16.bf16.f32 "
        "{%0,%1,%2,%3}, {%4,%5,%6,%7}, {%8,%9}, {%0,%1,%2,%3};"
        : "+f"(c[0]), "+f"(c[1]), "+f"(c[2]), "+f"(c[3])
        : "r"(a[0]), "r"(a[1]), "r"(a[2]), "r"(a[3]), "r"(b[0]), "r"(b[1]));
}
__device__ __forceinline__ u32 smem_u32(const void* p) {
    u32 a;
    asm("{ .reg .u64 t; cvta.to.shared.u64 t, %1; cvt.u32.u64 %0, t; }"
        : "=r"(a) : "l"(p));
    return a;
}

// ---------------------------------------------------------------------------
// Kernel 0: prep split-bf16 transposed weights (tiny).
// ---------------------------------------------------------------------------
__global__ __launch_bounds__(256) void wprep_kernel(const float* __restrict__ W)
{
    int idx = blockIdx.x * 256 + threadIdx.x;
    if (idx >= 192 * CDIM) return;
    int n = idx >> 10, k = idx & 1023;
    float w = W[(size_t)k * 192 + n];
    __nv_bfloat16 hi = __float2bfloat16(w);
    g_wt_hi[(size_t)n * CDIM + k] = hi;
    g_wt_lo[(size_t)n * CDIM + k] = __float2bfloat16(w - __bfloat162float(hi));
}

// ---------------------------------------------------------------------------
// Kernel 1: QKV projection, single wave, DOUBLE-BUFFERED pipeline.
// BM=128, BN=192, BK=32, grid 128, 256 thr = 8 warps (4M x 2N).
// W tiles via cp.async (row stride 20 words: 16B-aligned dsts, conflict-free
// fragment reads); x via LDG->split->STS into the other buffer.
// ONE __syncthreads per stage; loads fully overlap MMA.
// ---------------------------------------------------------------------------
#define QKV_XHI 0
#define QKV_XLO 2176
#define QKV_WHI 4352
#define QKV_WLO 8192
#define QKV_BUF_WORDS 12032
#define QKV_SMEM_BYTES (2 * QKV_BUF_WORDS * 4)

__device__ __forceinline__ void qkv_cpW(u32 sb, u32 bufoff, int k0, int tid)
{
#pragma unroll
    for (int i = 0; i < 3; i++) {
        int idx = i * 256 + tid;              // 0..767
        int n = idx >> 2, ch = idx & 3;
        u32 dhi = sb + (bufoff + QKV_WHI + n * 20 + ch * 4) * 4;
        u32 dlo = sb + (bufoff + QKV_WLO + n * 20 + ch * 4) * 4;
        const void* shi = g_wt_hi + (size_t)n * CDIM + k0 + ch * 8;
        const void* slo = g_wt_lo + (size_t)n * CDIM + k0 + ch * 8;
        asm volatile("cp.async.ca.shared.global [%0], [%1], 16;"
                     :: "r"(dhi), "l"(shi) : "memory");
        asm volatile("cp.async.ca.shared.global [%0], [%1], 16;"
                     :: "r"(dlo), "l"(slo) : "memory");
    }
    asm volatile("cp.async.commit_group;" ::: "memory");
}

__global__ __launch_bounds__(256) void qkv_mma_kernel(
    const float* __restrict__ x, const float* __restrict__ bias)
{
    extern __shared__ u32 qsm[];
    const u32 sb = smem_u32(qsm);

    const int tid  = threadIdx.x;
    const int wid  = tid >> 5, lane = tid & 31;
    const int g    = lane >> 2, t = lane & 3;
    const int bm   = blockIdx.x;
    const int wm0  = (wid & 3) * 32;
    const int wn0  = (wid >> 2) * 96;

    const int xrow = tid >> 1;
    const int xfc  = (tid & 1) * 16;
    const float* xsrc = x + ((size_t)(bm * 128 + xrow)) * CDIM + xfc;

    float c[2][12][4];
#pragma unroll
    for (int i = 0; i < 2; i++)
#pragma unroll
        for (int j = 0; j < 12; j++)
#pragma unroll
            for (int q = 0; q < 4; q++) c[i][j][q] = 0.f;

    float4 xv[4];
    // ---- prologue: stage 0 into buffer 0 ----
#pragma unroll
    for (int q = 0; q < 4; q++)
        xv[q] = *reinterpret_cast<const float4*>(xsrc + q * 4);
    qkv_cpW(sb, 0, 0, tid);
    {
        u32* dh = qsm + QKV_XHI + xrow * 17 + (xfc >> 1);
        u32* dl = qsm + QKV_XLO + xrow * 17 + (xfc >> 1);
#pragma unroll
        for (int q = 0; q < 4; q++) {
            u32 h0, l0, h1, l1;
            split2(xv[q].x, xv[q].y, h0, l0);
            split2(xv[q].z, xv[q].w, h1, l1);
            dh[q * 2] = h0; dh[q * 2 + 1] = h1;
            dl[q * 2] = l0; dl[q * 2 + 1] = l1;
        }
    }
    asm volatile("cp.async.wait_group 0;" ::: "memory");
    __syncthreads();

    for (int st = 0; st < 32; st++) {
        const u32 bufoff = (u32)(st & 1) * QKV_BUF_WORDS;
        const u32 nxtoff = bufoff ^ QKV_BUF_WORDS;

        if (st < 31) {
            const int k1 = (st + 1) * 32;
#pragma unroll
            for (int q = 0; q < 4; q++)
                xv[q] = *reinterpret_cast<const float4*>(xsrc + k1 + q * 4);
            qkv_cpW(sb, nxtoff, k1, tid);
        }

        // ---- MMA on current buffer ----
        const u32* xhi = qsm + bufoff + QKV_XHI;
        const u32* xlo = qsm + bufoff + QKV_XLO;
        const u32* whi = qsm + bufoff + QKV_WHI;
        const u32* wlo = qsm + bufoff + QKV_WLO;
#pragma unroll
        for (int ks = 0; ks < 2; ks++) {
            const int ko = ks * 8 + t;
            u32 ah[2][4], al[2][4];
#pragma unroll
            for (int i = 0; i < 2; i++) {
                const int rb = (wm0 + i * 16 + g) * 17 + ko;
                ah[i][0] = xhi[rb];
                ah[i][1] = xhi[rb + 8 * 17];
                ah[i][2] = xhi[rb + 4];
                ah[i][3] = xhi[rb + 8 * 17 + 4];
                al[i][0] = xlo[rb];
                al[i][1] = xlo[rb + 8 * 17];
                al[i][2] = xlo[rb + 4];
                al[i][3] = xlo[rb + 8 * 17 + 4];
            }
#pragma unroll
            for (int j = 0; j < 12; j++) {
                const int nb = (wn0 + j * 8 + g) * 20 + ko;
                u32 bh[2] = { whi[nb], whi[nb + 4] };
                u32 bl[2] = { wlo[nb], wlo[nb + 4] };
#pragma unroll
                for (int i = 0; i < 2; i++) {
                    mma16816(c[i][j], ah[i], bh);
                    mma16816(c[i][j], al[i], bh);
                    mma16816(c[i][j], ah[i], bl);
                }
            }
        }

        if (st < 31) {
            u32* dh = qsm + nxtoff + QKV_XHI + xrow * 17 + (xfc >> 1);
            u32* dl = qsm + nxtoff + QKV_XLO + xrow * 17 + (xfc >> 1);
#pragma unroll
            for (int q = 0; q < 4; q++) {
                u32 h0, l0, h1, l1;
                split2(xv[q].x, xv[q].y, h0, l0);
                split2(xv[q].z, xv[q].w, h1, l1);
                dh[q * 2] = h0; dh[q * 2 + 1] = h1;
                dl[q * 2] = l0; dl[q * 2 + 1] = l1;
            }
            asm volatile("cp.async.wait_group 0;" ::: "memory");
        }
        __syncthreads();
    }

    // ---- epilogue: +bias, split to bf16 hi/lo, store (v transposed) ----
#pragma unroll
    for (int i = 0; i < 2; i++) {
        const int row0 = bm * 128 + wm0 + i * 16 + g;
#pragma unroll
        for (int j = 0; j < 12; j++) {
            const int colg = wn0 + j * 8 + 2 * t;
            const int blk  = colg >> 6;          // 0=k, 1=q, 2=v
            const int col  = colg & 63;
            const float bz0 = bias[colg], bz1 = bias[colg + 1];
            float v00 = c[i][j][0] + bz0, v01 = c[i][j][1] + bz1;
            float v10 = c[i][j][2] + bz0, v11 = c[i][j][3] + bz1;
            if (blk == 2) {
                const int bidx = row0 >> 11;
                const int tt   = row0 & 2047;
                size_t p0 = (size_t)(bidx * 64 + col) * 2048 + tt;
                size_t p1 = p0 + 2048;
                __nv_bfloat16 h;
                h = __float2bfloat16(v00); g_vth[p0] = h;
                g_vtl[p0] = __float2bfloat16(v00 - __bfloat162float(h));
                h = __float2bfloat16(v01); g_vth[p1] = h;
                g_vtl[p1] = __float2bfloat16(v01 - __bfloat162float(h));
                h = __float2bfloat16(v10); g_vth[p0 + 8] = h;
                g_vtl[p0 + 8] = __float2bfloat16(v10 - __bfloat162float(h));
                h = __float2bfloat16(v11); g_vth[p1 + 8] = h;
                g_vtl[p1 + 8] = __float2bfloat16(v11 - __bfloat162float(h));
            } else {
                __nv_bfloat16* dh = blk ? g_qh : g_kh;
                __nv_bfloat16* dl = blk ? g_ql : g_kl;
                const float sc = blk ? 0.125f : 1.0f;
                v00 *= sc; v01 *= sc; v10 *= sc; v11 *= sc;
                u32 h0, l0, h1, l1;
                split2(v00, v01, h0, l0);
                split2(v10, v11, h1, l1);
                *reinterpret_cast<u32*>(dh + (size_t)row0 * HD + col) = h0;
                *reinterpret_cast<u32*>(dl + (size_t)row0 * HD + col) = l0;
                *reinterpret_cast<u32*>(dh + (size_t)(row0 + 8) * HD + col) = h1;
                *reinterpret_cast<u32*>(dl + (size_t)(row0 + 8) * HD + col) = l1;
            }
        }
    }
}

// ---------------------------------------------------------------------------
// Kernel 2: causal flash attention on HMMA, THREE-way split-K warp groups.
// 384 thr = 3 groups of 4 warps; group gp handles key tiles kt == gp (mod 3),
// private double-buffered smem + private (m,l,O); 3-way merge at the end
// (merge staging reuses group-0's buffers). Pairing (qt, 31-qt): grid (16,8).
// ---------------------------------------------------------------------------
#define KTW   36
#define PLANE (64 * KTW)                 // words per operand plane
#define BUF_WORDS (4 * PLANE)            // one buffer: 4 planes
#define GRP_WORDS (2 * BUF_WORDS)        // double buffered
#define NGRP 3
#define MO_STR 66
#define ATTN_SMEM (NGRP * GRP_WORDS * 4) // 221184 B

__device__ __forceinline__ void barg(int id) {
    asm volatile("bar.sync %0, 128;" :: "r"(id) : "memory");
}

__device__ __forceinline__ void cp_tile(u32 base_bytes, int t0, int ltid,
    const __nv_bfloat16* kh_g, const __nv_bfloat16* kl_g,
    const __nv_bfloat16* vh_g, const __nv_bfloat16* vl_g)
{
#pragma unroll
    for (int i = 0; i < 4; i++) {
        int id = i * 128 + ltid;
        int row = id >> 3, ch = id & 7;
        u32 soff = (u32)(row * KTW + ch * 4) * 4;
        const void* s1 = kh_g + (size_t)(t0 + row) * HD + ch * 8;
        const void* s2 = kl_g + (size_t)(t0 + row) * HD + ch * 8;
        const void* s3 = vh_g + (size_t)row * TSEQ + t0 + ch * 8;
        const void* s4 = vl_g + (size_t)row * TSEQ + t0 + ch * 8;
        asm volatile("cp.async.ca.shared.global [%0], [%1], 16;"
                     :: "r"(base_bytes + 0 * PLANE * 4 + soff), "l"(s1) : "memory");
        asm volatile("cp.async.ca.shared.global [%0], [%1], 16;"
                     :: "r"(base_bytes + 1 * PLANE * 4 + soff), "l"(s2) : "memory");
        asm volatile("cp.async.ca.shared.global [%0], [%1], 16;"
                     :: "r"(base_bytes + 2 * PLANE * 4 + soff), "l"(s3) : "memory");
        asm volatile("cp.async.ca.shared.global [%0], [%1], 16;"
                     :: "r"(base_bytes + 3 * PLANE * 4 + soff), "l"(s4) : "memory");
    }
    asm volatile("cp.async.commit_group;" ::: "memory");
}

__global__ __launch_bounds__(384, 1) void attn_hmma_kernel(float* __restrict__ out)
{
    extern __shared__ u32 smem_dyn[];
    const u32 sbase = smem_u32(smem_dyn);

    const int tid = threadIdx.x;
    const int w = tid >> 5, lane = tid & 31;
    const int gp = w >> 2;              // warp group 0/1/2
    const int wg = w & 3;
    const int g = lane >> 2, t = lane & 3;
    const int ltid = tid & 127;
    const int bb = blockIdx.y, bx = blockIdx.x;

    const __nv_bfloat16* qh_g = g_qh + (size_t)bb * TSEQ * HD;
    const __nv_bfloat16* ql_g = g_ql + (size_t)bb * TSEQ * HD;
    const __nv_bfloat16* kh_g = g_kh + (size_t)bb * TSEQ * HD;
    const __nv_bfloat16* kl_g = g_kl + (size_t)bb * TSEQ * HD;
    const __nv_bfloat16* vh_g = g_vth + (size_t)bb * HD * TSEQ;
    const __nv_bfloat16* vl_g = g_vtl + (size_t)bb * HD * TSEQ;

    const u32 gbase = sbase + (u32)gp * GRP_WORDS * 4;
    // merge staging reuses group-0 buffer space (valid after __syncthreads)
    float* mo  = (float*)smem_dyn;                 // [2][64][MO_STR]
    float* mmv = mo + 2 * 64 * MO_STR;             // [2][64]
    float* mlv = mmv + 2 * 64;                     // [2][64]

    for (int half = 0; half < 2; half++) {
        const int qt = half ? 31 - bx : bx;
        const int qrow0 = qt * 64;
        const int r0 = wg * 16 + g;      // local row within 64-row q tile

        // Q fragments (A operand)
        u32 qh[4][4], ql[4][4];
#pragma unroll
        for (int kk = 0; kk < 4; kk++) {
            const size_t b0 = (size_t)(qrow0 + r0) * HD + kk * 16 + 2 * t;
            const size_t b1 = b0 + 8 * HD;
            qh[kk][0] = *(const u32*)(qh_g + b0);
            qh[kk][1] = *(const u32*)(qh_g + b1);
            qh[kk][2] = *(const u32*)(qh_g + b0 + 8);
            qh[kk][3] = *(const u32*)(qh_g + b1 + 8);
            ql[kk][0] = *(const u32*)(ql_g + b0);
            ql[kk][1] = *(const u32*)(ql_g + b1);
            ql[kk][2] = *(const u32*)(ql_g + b0 + 8);
            ql[kk][3] = *(const u32*)(ql_g + b1 + 8);
        }

        float o[8][4];
#pragma unroll
        for (int nt = 0; nt < 8; nt++)
#pragma unroll
            for (int q = 0; q < 4; q++) o[nt][q] = 0.f;
        float m0 = -1e30f, m1 = -1e30f, l0 = 0.f, l1 = 0.f;

        const int n_t = (qt >= gp) ? ((qt - gp) / 3) + 1 : 0;
        if (n_t > 0) cp_tile(gbase, gp * 64, ltid, kh_g, kl_g, vh_g, vl_g);

        for (int i = 0; i < n_t; i++) {
            const int kt = gp + 3 * i;
            const int t0 = kt * 64;
            if (i + 1 < n_t) {
                cp_tile(gbase + (u32)((i + 1) & 1) * BUF_WORDS * 4,
                        (gp + 3 * (i + 1)) * 64, ltid, kh_g, kl_g, vh_g, vl_g);
                asm volatile("cp.async.wait_group 1;" ::: "memory");
            } else {
                asm volatile("cp.async.wait_group 0;" ::: "memory");
            }
            barg(1 + gp);

            const u32* buf = smem_dyn + gp * GRP_WORDS + (u32)(i & 1) * BUF_WORDS;
            const u32* kh_s = buf;
            const u32* kl_s = buf + PLANE;
            const u32* vh_s = buf + 2 * PLANE;
            const u32* vl_s = buf + 3 * PLANE;

            // ---- GEMM1: S = Q @ K^T ----
            float s[8][4];
#pragma unroll
            for (int nt = 0; nt < 8; nt++)
#pragma unroll
                for (int q = 0; q < 4; q++) s[nt][q] = 0.f;
#pragma unroll
            for (int kk = 0; kk < 4; kk++) {
#pragma unroll
                for (int nt = 0; nt < 8; nt++) {
                    const int bi = (nt * 8 + g) * KTW + kk * 8 + t;
                    u32 bh[2] = { kh_s[bi], kh_s[bi + 4] };
                    u32 bl[2] = { kl_s[bi], kl_s[bi + 4] };
                    mma16816(s[nt], qh[kk], bh);
                    mma16816(s[nt], ql[kk], bh);
                    mma16816(s[nt], qh[kk], bl);
                }
            }

            if (kt == qt) {   // diagonal tile: causal mask
                const int rg = qrow0 + r0;
#pragma unroll
                for (int nt = 0; nt < 8; nt++) {
                    const int col = t0 + nt * 8 + 2 * t;
                    if (col     > rg)     s[nt][0] = -1e30f;
                    if (col + 1 > rg)     s[nt][1] = -1e30f;
                    if (col     > rg + 8) s[nt][2] = -1e30f;
                    if (col + 1 > rg + 8) s[nt][3] = -1e30f;
                }
            }

            // ---- streaming softmax ----
            float mx0 = -1e30f, mx1 = -1e30f;
#pragma unroll
            for (int nt = 0; nt < 8; nt++) {
                mx0 = fmaxf(mx0, fmaxf(s[nt][0], s[nt][1]));
                mx1 = fmaxf(mx1, fmaxf(s[nt][2], s[nt][3]));
            }
            mx0 = fmaxf(mx0, __shfl_xor_sync(0xffffffffu, mx0, 1));
            mx0 = fmaxf(mx0, __shfl_xor_sync(0xffffffffu, mx0, 2));
            mx1 = fmaxf(mx1, __shfl_xor_sync(0xffffffffu, mx1, 1));
            mx1 = fmaxf(mx1, __shfl_xor_sync(0xffffffffu, mx1, 2));
            const float mn0 = fmaxf(m0, mx0), mn1 = fmaxf(m1, mx1);
            const float c0r = __expf(m0 - mn0), c1r = __expf(m1 - mn1);
            m0 = mn0; m1 = mn1;

            float s0 = 0.f, s1 = 0.f;
            u32 ph[4][4], pl[4][4];
#pragma unroll
            for (int q2 = 0; q2 < 4; q2++) {
                float p00 = __expf(s[2*q2][0]   - mn0), p01 = __expf(s[2*q2][1]   - mn0);
                float p02 = __expf(s[2*q2][2]   - mn1), p03 = __expf(s[2*q2][3]   - mn1);
                float p10 = __expf(s[2*q2+1][0] - mn0), p11 = __expf(s[2*q2+1][1] - mn0);
                float p12 = __expf(s[2*q2+1][2] - mn1), p13 = __expf(s[2*q2+1][3] - mn1);
                s0 += (p00 + p01) + (p10 + p11);
                s1 += (p02 + p03) + (p12 + p13);
                split2(p00, p01, ph[q2][0], pl[q2][0]);
                split2(p02, p03, ph[q2][1], pl[q2][1]);
                split2(p10, p11, ph[q2][2], pl[q2][2]);
                split2(p12, p13, ph[q2][3], pl[q2][3]);
            }
            s0 += __shfl_xor_sync(0xffffffffu, s0, 1);
            s0 += __shfl_xor_sync(0xffffffffu, s0, 2);
            s1 += __shfl_xor_sync(0xffffffffu, s1, 1);
            s1 += __shfl_xor_sync(0xffffffffu, s1, 2);
            l0 = l0 * c0r + s0;
            l1 = l1 * c1r + s1;

#pragma unroll
            for (int nt = 0; nt < 8; nt++) {
                o[nt][0] *= c0r; o[nt][1] *= c0r;
                o[nt][2] *= c1r; o[nt][3] *= c1r;
            }

            // ---- GEMM2: O += P @ V ----
#pragma unroll
            for (int kk = 0; kk < 4; kk++) {
#pragma unroll
                for (int nt = 0; nt < 8; nt++) {
                    const int bi = (nt * 8 + g) * KTW + kk * 8 + t;
                    u32 bh[2] = { vh_s[bi], vh_s[bi + 4] };
                    u32 bl[2] = { vl_s[bi], vl_s[bi + 4] };
                    mma16816(o[nt], ph[kk], bh);
                    mma16816(o[nt], pl[kk], bh);
                    mma16816(o[nt], ph[kk], bl);
                }
            }
            barg(1 + gp);
        }

        // ---- 3-way merge (staging reuses group-0 buffers) ----
        __syncthreads();
        if (gp >= 1) {
            const int gi = gp - 1;
            float* mog = mo + gi * 64 * MO_STR;
            const int ra = r0, rb = r0 + 8;
#pragma unroll
            for (int nt = 0; nt < 8; nt++) {
                const int cc = nt * 8 + 2 * t;
                mog[ra * MO_STR + cc]     = o[nt][0];
                mog[ra * MO_STR + cc + 1] = o[nt][1];
                mog[rb * MO_STR + cc]     = o[nt][2];
                mog[rb * MO_STR + cc + 1] = o[nt][3];
            }
            if (t == 0) {
                mmv[gi * 64 + ra] = m0; mlv[gi * 64 + ra] = l0;
                mmv[gi * 64 + rb] = m1; mlv[gi * 64 + rb] = l1;
            }
        }
        __syncthreads();
        if (gp == 0) {
            const int ra = r0, rb = r0 + 8;
            const float m1a = mmv[ra],      l1a = mlv[ra];
            const float m2a = mmv[64 + ra], l2a = mlv[64 + ra];
            const float m1b = mmv[rb],      l1b = mlv[rb];
            const float m2b = mmv[64 + rb], l2b = mlv[64 + rb];
            const float msA = fmaxf(m0, fmaxf(m1a, m2a));
            const float msB = fmaxf(m1, fmaxf(m1b, m2b));
            const float f0A = __expf(m0 - msA), f1A = __expf(m1a - msA), f2A = __expf(m2a - msA);
            const float f0B = __expf(m1 - msB), f1B = __expf(m1b - msB), f2B = __expf(m2b - msB);
            const float invA = 1.f / (l0 * f0A + l1a * f1A + l2a * f2A);
            const float invB = 1.f / (l1 * f0B + l1b * f1B + l2b * f2B);
            const float* mo1 = mo;
            const float* mo2 = mo + 64 * MO_STR;
            float* orow0 = out + ((size_t)bb * TSEQ + qrow0 + ra) * HD;
            float* orow1 = out + ((size_t)bb * TSEQ + qrow0 + rb) * HD;
#pragma unroll
            for (int nt = 0; nt < 8; nt++) {
                const int cc = nt * 8 + 2 * t;
                float2 oa, ob;
                oa.x = (o[nt][0] * f0A + mo1[ra * MO_STR + cc]     * f1A
                                       + mo2[ra * MO_STR + cc]     * f2A) * invA;
                oa.y = (o[nt][1] * f0A + mo1[ra * MO_STR + cc + 1] * f1A
                                       + mo2[ra * MO_STR + cc + 1] * f2A) * invA;
                ob.x = (o[nt][2] * f0B + mo1[rb * MO_STR + cc]     * f1B
                                       + mo2[rb * MO_STR + cc]     * f2B) * invB;
                ob.y = (o[nt][3] * f0B + mo1[rb * MO_STR + cc + 1] * f1B
                                       + mo2[rb * MO_STR + cc + 1] * f2B) * invB;
                *reinterpret_cast<float2*>(orow0 + cc) = oa;
                *reinterpret_cast<float2*>(orow1 + cc) = ob;
            }
        }
        __syncthreads();   // merge region free before next half reuses buffers
    }
}

// ---------------------------------------------------------------------------
extern "C" void kernel_launch(void* const* d_in, const int* in_sizes, int n_in,
                              void* d_out, int out_size)
{
    const float* x = (const float*)d_in[0];
    const float* W = (const float*)d_in[1];
    const float* b = (const float*)d_in[2];
    float* out = (float*)d_out;

    (void)in_sizes; (void)n_in; (void)out_size;

    static int attr_set = 0;
    if (!attr_set) {
        cudaFuncSetAttribute(attn_hmma_kernel,
                             cudaFuncAttributeMaxDynamicSharedMemorySize, ATTN_SMEM);
        cudaFuncSetAttribute(qkv_mma_kernel,
                             cudaFuncAttributeMaxDynamicSharedMemorySize, QKV_SMEM_BYTES);
        attr_set = 1;
    }

    wprep_kernel<<<(192 * CDIM + 255) / 256, 256>>>(W);
    qkv_mma_kernel<<<128, 256, QKV_SMEM_BYTES>>>(x, b);

    dim3 g2(16, BSZ);
    attn_hmma_kernel<<<g2, 384, ATTN_SMEM>>>(out);
}

// round 11
// speedup vs baseline: 3.3954x; 1.0179x over previous
#include <cuda_runtime.h>
#include <cuda_bf16.h>
#include <math.h>
#include <stdint.h>

#define BSZ   8
#define TSEQ  2048
#define CDIM  1024
#define HD    64

typedef unsigned int u32;

// split-bf16 W transposed ([192][1024])
__device__ __align__(16) __nv_bfloat16 g_wt_hi[192 * CDIM];
__device__ __align__(16) __nv_bfloat16 g_wt_lo[192 * CDIM];

// split-bf16 attention operands (written by qkv kernel)
__device__ __align__(16) __nv_bfloat16 g_qh[BSZ * TSEQ * HD];  // pre-scaled 0.125
__device__ __align__(16) __nv_bfloat16 g_ql[BSZ * TSEQ * HD];
__device__ __align__(16) __nv_bfloat16 g_kh[BSZ * TSEQ * HD];
__device__ __align__(16) __nv_bfloat16 g_kl[BSZ * TSEQ * HD];
__device__ __align__(16) __nv_bfloat16 g_vth[BSZ * HD * TSEQ]; // [b][d][t]
__device__ __align__(16) __nv_bfloat16 g_vtl[BSZ * HD * TSEQ];

__device__ __forceinline__ u32 bf2(float lo, float hi) {
    u32 r; asm("cvt.rn.bf16x2.f32 %0, %1, %2;" : "=r"(r) : "f"(hi), "f"(lo));
    return r;
}
__device__ __forceinline__ void split2(float a, float b, u32& hi, u32& lo) {
    hi = bf2(a, b);
    float ha = __uint_as_float(hi << 16);
    float hb = __uint_as_float(hi & 0xffff0000u);
    lo = bf2(a - ha, b - hb);
}
__device__ __forceinline__ void mma16816(float c[4], const u32 a[4], const u32 b[2]) {
    asm volatile(
        "mma.sync.aligned.m16n8k16.row.col.f32.bf16.bf16.f32 "
        "{%0,%1,%2,%3}, {%4,%5,%6,%7}, {%8,%9}, {%0,%1,%2,%3};"
        : "+f"(c[0]), "+f"(c[1]), "+f"(c[2]), "+f"(c[3])
        : "r"(a[0]), "r"(a[1]), "r"(a[2]), "r"(a[3]), "r"(b[0]), "r"(b[1]));
}
__device__ __forceinline__ void ldm_x4(u32* r, u32 addr) {
    asm volatile("ldmatrix.sync.aligned.m8n8.x4.shared.b16 {%0,%1,%2,%3}, [%4];"
                 : "=r"(r[0]), "=r"(r[1]), "=r"(r[2]), "=r"(r[3]) : "r"(addr));
}
__device__ __forceinline__ u32 smem_u32(const void* p) {
    u32 a;
    asm("{ .reg .u64 t; cvta.to.shared.u64 t, %1; cvt.u32.u64 %0, t; }"
        : "=r"(a) : "l"(p));
    return a;
}

// ---------------------------------------------------------------------------
// Kernel 0: prep split-bf16 transposed weights (tiny).
// ---------------------------------------------------------------------------
__global__ __launch_bounds__(256) void wprep_kernel(const float* __restrict__ W)
{
    int idx = blockIdx.x * 256 + threadIdx.x;
    if (idx >= 192 * CDIM) return;
    int n = idx >> 10, k = idx & 1023;
    float w = W[(size_t)k * 192 + n];
    __nv_bfloat16 hi = __float2bfloat16(w);
    g_wt_hi[(size_t)n * CDIM + k] = hi;
    g_wt_lo[(size_t)n * CDIM + k] = __float2bfloat16(w - __bfloat162float(hi));
}

// ---------------------------------------------------------------------------
// Kernel 1: QKV projection, single wave, double-buffered, ldmatrix fragments.
// BM=128, BN=192, BK=32, grid 128, 256 thr = 8 warps (4M x 2N).
// smem row stride 20 words (80B: 16B-aligned rows, ldmatrix conflict-free).
// ---------------------------------------------------------------------------
#define QKV_XHI 0
#define QKV_XLO 2560
#define QKV_WHI 5120
#define QKV_WLO 8960
#define QKV_BUF_WORDS 12800
#define QKV_SMEM_BYTES (2 * QKV_BUF_WORDS * 4)   // 102400

__device__ __forceinline__ void qkv_cpW(u32 sb, u32 bufoff, int k0, int tid)
{
#pragma unroll
    for (int i = 0; i < 3; i++) {
        int idx = i * 256 + tid;              // 0..767
        int n = idx >> 2, ch = idx & 3;
        u32 dhi = sb + (bufoff + QKV_WHI + n * 20 + ch * 4) * 4;
        u32 dlo = sb + (bufoff + QKV_WLO + n * 20 + ch * 4) * 4;
        const void* shi = g_wt_hi + (size_t)n * CDIM + k0 + ch * 8;
        const void* slo = g_wt_lo + (size_t)n * CDIM + k0 + ch * 8;
        asm volatile("cp.async.ca.shared.global [%0], [%1], 16;"
                     :: "r"(dhi), "l"(shi) : "memory");
        asm volatile("cp.async.ca.shared.global [%0], [%1], 16;"
                     :: "r"(dlo), "l"(slo) : "memory");
    }
    asm volatile("cp.async.commit_group;" ::: "memory");
}

__global__ __launch_bounds__(256) void qkv_mma_kernel(
    const float* __restrict__ x, const float* __restrict__ bias)
{
    extern __shared__ u32 qsm[];
    const u32 sb = smem_u32(qsm);

    const int tid  = threadIdx.x;
    const int wid  = tid >> 5, lane = tid & 31;
    const int g    = lane >> 2, t = lane & 3;
    const int bm   = blockIdx.x;
    const int wm0  = (wid & 3) * 32;
    const int wn0  = (wid >> 2) * 96;

    // ldmatrix per-thread coords
    const int arow = lane & 7;
    const int tsel = lane >> 3;           // 0..3
    // A-frag word offset (within x plane), for (i, ks):
    //   ((wm0 + i*16 + (tsel&1)*8 + arow)*20 + ks*8 + (tsel>>1)*4)
    // B-frag word offset (within W plane), for j:
    //   ((wn0 + j*8 + arow)*20 + tsel*4)

    const int xrow = tid >> 1;
    const int xfc  = (tid & 1) * 16;
    const float* xsrc = x + ((size_t)(bm * 128 + xrow)) * CDIM + xfc;
    const u32 xw0 = xrow * 20 + (tid & 1) * 8;   // word offset of this thread's x chunk

    float c[2][12][4];
#pragma unroll
    for (int i = 0; i < 2; i++)
#pragma unroll
        for (int j = 0; j < 12; j++)
#pragma unroll
            for (int q = 0; q < 4; q++) c[i][j][q] = 0.f;

    float4 xv[4];
    // ---- prologue: stage 0 into buffer 0 ----
#pragma unroll
    for (int q = 0; q < 4; q++)
        xv[q] = *reinterpret_cast<const float4*>(xsrc + q * 4);
    qkv_cpW(sb, 0, 0, tid);
    {
        u32* dh = qsm + QKV_XHI + xw0;
        u32* dl = qsm + QKV_XLO + xw0;
#pragma unroll
        for (int q = 0; q < 4; q++) {
            u32 h0, l0, h1, l1;
            split2(xv[q].x, xv[q].y, h0, l0);
            split2(xv[q].z, xv[q].w, h1, l1);
            dh[q * 2] = h0; dh[q * 2 + 1] = h1;
            dl[q * 2] = l0; dl[q * 2 + 1] = l1;
        }
    }
    asm volatile("cp.async.wait_group 0;" ::: "memory");
    __syncthreads();

    for (int st = 0; st < 32; st++) {
        const u32 bufoff = (u32)(st & 1) * QKV_BUF_WORDS;
        const u32 nxtoff = bufoff ^ QKV_BUF_WORDS;

        if (st < 31) {
            const int k1 = (st + 1) * 32;
#pragma unroll
            for (int q = 0; q < 4; q++)
                xv[q] = *reinterpret_cast<const float4*>(xsrc + k1 + q * 4);
            qkv_cpW(sb, nxtoff, k1, tid);
        }

        // ---- MMA on current buffer (ldmatrix fragments) ----
        const u32 base = sb + bufoff * 4;
        u32 Ah[2][2][4], Al[2][2][4];
#pragma unroll
        for (int i = 0; i < 2; i++)
#pragma unroll
            for (int ks = 0; ks < 2; ks++) {
                const u32 aoff = (u32)((wm0 + i * 16 + ((tsel & 1) << 3) + arow) * 20
                                       + ks * 8 + ((tsel >> 1) << 2)) * 4;
                ldm_x4(Ah[i][ks], base + QKV_XHI * 4 + aoff);
                ldm_x4(Al[i][ks], base + QKV_XLO * 4 + aoff);
            }
#pragma unroll
        for (int j = 0; j < 12; j++) {
            const u32 boff = (u32)((wn0 + j * 8 + arow) * 20 + tsel * 4) * 4;
            u32 bh[4], bl[4];
            ldm_x4(bh, base + QKV_WHI * 4 + boff);
            ldm_x4(bl, base + QKV_WLO * 4 + boff);
#pragma unroll
            for (int ks = 0; ks < 2; ks++)
#pragma unroll
                for (int i = 0; i < 2; i++) {
                    mma16816(c[i][j], Ah[i][ks], bh + ks * 2);
                    mma16816(c[i][j], Al[i][ks], bh + ks * 2);
                    mma16816(c[i][j], Ah[i][ks], bl + ks * 2);
                }
        }

        if (st < 31) {
            u32* dh = qsm + nxtoff + QKV_XHI + xw0;
            u32* dl = qsm + nxtoff + QKV_XLO + xw0;
#pragma unroll
            for (int q = 0; q < 4; q++) {
                u32 h0, l0, h1, l1;
                split2(xv[q].x, xv[q].y, h0, l0);
                split2(xv[q].z, xv[q].w, h1, l1);
                dh[q * 2] = h0; dh[q * 2 + 1] = h1;
                dl[q * 2] = l0; dl[q * 2 + 1] = l1;
            }
            asm volatile("cp.async.wait_group 0;" ::: "memory");
        }
        __syncthreads();
    }

    // ---- epilogue: +bias, split to bf16 hi/lo, store (v transposed) ----
#pragma unroll
    for (int i = 0; i < 2; i++) {
        const int row0 = bm * 128 + wm0 + i * 16 + g;
#pragma unroll
        for (int j = 0; j < 12; j++) {
            const int colg = wn0 + j * 8 + 2 * t;
            const int blk  = colg >> 6;          // 0=k, 1=q, 2=v
            const int col  = colg & 63;
            const float bz0 = bias[colg], bz1 = bias[colg + 1];
            float v00 = c[i][j][0] + bz0, v01 = c[i][j][1] + bz1;
            float v10 = c[i][j][2] + bz0, v11 = c[i][j][3] + bz1;
            if (blk == 2) {
                const int bidx = row0 >> 11;
                const int tt   = row0 & 2047;
                size_t p0 = (size_t)(bidx * 64 + col) * 2048 + tt;
                size_t p1 = p0 + 2048;
                __nv_bfloat16 h;
                h = __float2bfloat16(v00); g_vth[p0] = h;
                g_vtl[p0] = __float2bfloat16(v00 - __bfloat162float(h));
                h = __float2bfloat16(v01); g_vth[p1] = h;
                g_vtl[p1] = __float2bfloat16(v01 - __bfloat162float(h));
                h = __float2bfloat16(v10); g_vth[p0 + 8] = h;
                g_vtl[p0 + 8] = __float2bfloat16(v10 - __bfloat162float(h));
                h = __float2bfloat16(v11); g_vth[p1 + 8] = h;
                g_vtl[p1 + 8] = __float2bfloat16(v11 - __bfloat162float(h));
            } else {
                __nv_bfloat16* dh = blk ? g_qh : g_kh;
                __nv_bfloat16* dl = blk ? g_ql : g_kl;
                const float sc = blk ? 0.125f : 1.0f;
                v00 *= sc; v01 *= sc; v10 *= sc; v11 *= sc;
                u32 h0, l0, h1, l1;
                split2(v00, v01, h0, l0);
                split2(v10, v11, h1, l1);
                *reinterpret_cast<u32*>(dh + (size_t)row0 * HD + col) = h0;
                *reinterpret_cast<u32*>(dl + (size_t)row0 * HD + col) = l0;
                *reinterpret_cast<u32*>(dh + (size_t)(row0 + 8) * HD + col) = h1;
                *reinterpret_cast<u32*>(dl + (size_t)(row0 + 8) * HD + col) = l1;
            }
        }
    }
}

// ---------------------------------------------------------------------------
// Kernel 2: causal flash attention, HMMA + ldmatrix, 3-way split-K groups.
// 384 thr = 3 groups of 4 warps; group gp handles kt == gp (mod 3).
// ---------------------------------------------------------------------------
#define KTW   36
#define PLANE (64 * KTW)
#define BUF_WORDS (4 * PLANE)
#define GRP_WORDS (2 * BUF_WORDS)
#define NGRP 3
#define MO_STR 66
#define ATTN_SMEM (NGRP * GRP_WORDS * 4) // 221184 B

__device__ __forceinline__ void barg(int id) {
    asm volatile("bar.sync %0, 128;" :: "r"(id) : "memory");
}

__device__ __forceinline__ void cp_tile(u32 base_bytes, int t0, int ltid,
    const __nv_bfloat16* kh_g, const __nv_bfloat16* kl_g,
    const __nv_bfloat16* vh_g, const __nv_bfloat16* vl_g)
{
#pragma unroll
    for (int i = 0; i < 4; i++) {
        int id = i * 128 + ltid;
        int row = id >> 3, ch = id & 7;
        u32 soff = (u32)(row * KTW + ch * 4) * 4;
        const void* s1 = kh_g + (size_t)(t0 + row) * HD + ch * 8;
        const void* s2 = kl_g + (size_t)(t0 + row) * HD + ch * 8;
        const void* s3 = vh_g + (size_t)row * TSEQ + t0 + ch * 8;
        const void* s4 = vl_g + (size_t)row * TSEQ + t0 + ch * 8;
        asm volatile("cp.async.ca.shared.global [%0], [%1], 16;"
                     :: "r"(base_bytes + 0 * PLANE * 4 + soff), "l"(s1) : "memory");
        asm volatile("cp.async.ca.shared.global [%0], [%1], 16;"
                     :: "r"(base_bytes + 1 * PLANE * 4 + soff), "l"(s2) : "memory");
        asm volatile("cp.async.ca.shared.global [%0], [%1], 16;"
                     :: "r"(base_bytes + 2 * PLANE * 4 + soff), "l"(s3) : "memory");
        asm volatile("cp.async.ca.shared.global [%0], [%1], 16;"
                     :: "r"(base_bytes + 3 * PLANE * 4 + soff), "l"(s4) : "memory");
    }
    asm volatile("cp.async.commit_group;" ::: "memory");
}

__global__ __launch_bounds__(384, 1) void attn_hmma_kernel(float* __restrict__ out)
{
    extern __shared__ u32 smem_dyn[];
    const u32 sbase = smem_u32(smem_dyn);

    const int tid = threadIdx.x;
    const int w = tid >> 5, lane = tid & 31;
    const int gp = w >> 2;              // warp group 0/1/2
    const int wg = w & 3;
    const int g = lane >> 2, t = lane & 3;
    const int ltid = tid & 127;
    const int brow = lane & 7, bsel = lane >> 3;   // ldmatrix coords
    const int bb = blockIdx.y, bx = blockIdx.x;

    const __nv_bfloat16* qh_g = g_qh + (size_t)bb * TSEQ * HD;
    const __nv_bfloat16* ql_g = g_ql + (size_t)bb * TSEQ * HD;
    const __nv_bfloat16* kh_g = g_kh + (size_t)bb * TSEQ * HD;
    const __nv_bfloat16* kl_g = g_kl + (size_t)bb * TSEQ * HD;
    const __nv_bfloat16* vh_g = g_vth + (size_t)bb * HD * TSEQ;
    const __nv_bfloat16* vl_g = g_vtl + (size_t)bb * HD * TSEQ;

    const u32 gbase = sbase + (u32)gp * GRP_WORDS * 4;
    float* mo  = (float*)smem_dyn;                 // [2][64][MO_STR]
    float* mmv = mo + 2 * 64 * MO_STR;             // [2][64]
    float* mlv = mmv + 2 * 64;                     // [2][64]

    for (int half = 0; half < 2; half++) {
        const int qt = half ? 31 - bx : bx;
        const int qrow0 = qt * 64;
        const int r0 = wg * 16 + g;

        // Q fragments (A operand)
        u32 qh[4][4], ql[4][4];
#pragma unroll
        for (int kk = 0; kk < 4; kk++) {
            const size_t b0 = (size_t)(qrow0 + r0) * HD + kk * 16 + 2 * t;
            const size_t b1 = b0 + 8 * HD;
            qh[kk][0] = *(const u32*)(qh_g + b0);
            qh[kk][1] = *(const u32*)(qh_g + b1);
            qh[kk][2] = *(const u32*)(qh_g + b0 + 8);
            qh[kk][3] = *(const u32*)(qh_g + b1 + 8);
            ql[kk][0] = *(const u32*)(ql_g + b0);
            ql[kk][1] = *(const u32*)(ql_g + b1);
            ql[kk][2] = *(const u32*)(ql_g + b0 + 8);
            ql[kk][3] = *(const u32*)(ql_g + b1 + 8);
        }

        float o[8][4];
#pragma unroll
        for (int nt = 0; nt < 8; nt++)
#pragma unroll
            for (int q = 0; q < 4; q++) o[nt][q] = 0.f;
        float m0 = -1e30f, m1 = -1e30f, l0 = 0.f, l1 = 0.f;

        const int n_t = (qt >= gp) ? ((qt - gp) / 3) + 1 : 0;
        if (n_t > 0) cp_tile(gbase, gp * 64, ltid, kh_g, kl_g, vh_g, vl_g);

        for (int i = 0; i < n_t; i++) {
            const int kt = gp + 3 * i;
            const int t0 = kt * 64;
            if (i + 1 < n_t) {
                cp_tile(gbase + (u32)((i + 1) & 1) * BUF_WORDS * 4,
                        (gp + 3 * (i + 1)) * 64, ltid, kh_g, kl_g, vh_g, vl_g);
                asm volatile("cp.async.wait_group 1;" ::: "memory");
            } else {
                asm volatile("cp.async.wait_group 0;" ::: "memory");
            }
            barg(1 + gp);

            const u32 bufb = gbase + (u32)(i & 1) * BUF_WORDS * 4;
            // per-nt ldmatrix base offsets (bytes)
            // K plane at +0, KL at +PLANE*4, VH at +2*PLANE*4, VL at +3*PLANE*4

            // ---- GEMM1: S = Q @ K^T ----
            float s[8][4];
#pragma unroll
            for (int nt = 0; nt < 8; nt++)
#pragma unroll
                for (int q = 0; q < 4; q++) s[nt][q] = 0.f;
#pragma unroll
            for (int nt = 0; nt < 8; nt++) {
                const u32 bb0 = bufb + (u32)((nt * 8 + brow) * KTW + bsel * 4) * 4;
                u32 bh[4], bl[4];
                ldm_x4(bh, bb0);
                ldm_x4(bl, bb0 + PLANE * 4);
                mma16816(s[nt], qh[0], bh + 0);
                mma16816(s[nt], ql[0], bh + 0);
                mma16816(s[nt], qh[0], bl + 0);
                mma16816(s[nt], qh[1], bh + 2);
                mma16816(s[nt], ql[1], bh + 2);
                mma16816(s[nt], qh[1], bl + 2);
                ldm_x4(bh, bb0 + 64);            // +16 words: k half 1
                ldm_x4(bl, bb0 + PLANE * 4 + 64);
                mma16816(s[nt], qh[2], bh + 0);
                mma16816(s[nt], ql[2], bh + 0);
                mma16816(s[nt], qh[2], bl + 0);
                mma16816(s[nt], qh[3], bh + 2);
                mma16816(s[nt], ql[3], bh + 2);
                mma16816(s[nt], qh[3], bl + 2);
            }

            if (kt == qt) {   // diagonal tile: causal mask
                const int rg = qrow0 + r0;
#pragma unroll
                for (int nt = 0; nt < 8; nt++) {
                    const int col = t0 + nt * 8 + 2 * t;
                    if (col     > rg)     s[nt][0] = -1e30f;
                    if (col + 1 > rg)     s[nt][1] = -1e30f;
                    if (col     > rg + 8) s[nt][2] = -1e30f;
                    if (col + 1 > rg + 8) s[nt][3] = -1e30f;
                }
            }

            // ---- streaming softmax ----
            float mx0 = -1e30f, mx1 = -1e30f;
#pragma unroll
            for (int nt = 0; nt < 8; nt++) {
                mx0 = fmaxf(mx0, fmaxf(s[nt][0], s[nt][1]));
                mx1 = fmaxf(mx1, fmaxf(s[nt][2], s[nt][3]));
            }
            mx0 = fmaxf(mx0, __shfl_xor_sync(0xffffffffu, mx0, 1));
            mx0 = fmaxf(mx0, __shfl_xor_sync(0xffffffffu, mx0, 2));
            mx1 = fmaxf(mx1, __shfl_xor_sync(0xffffffffu, mx1, 1));
            mx1 = fmaxf(mx1, __shfl_xor_sync(0xffffffffu, mx1, 2));
            const float mn0 = fmaxf(m0, mx0), mn1 = fmaxf(m1, mx1);
            const float c0r = __expf(m0 - mn0), c1r = __expf(m1 - mn1);
            m0 = mn0; m1 = mn1;

            float s0 = 0.f, s1 = 0.f;
            u32 ph[4][4], pl[4][4];
#pragma unroll
            for (int q2 = 0; q2 < 4; q2++) {
                float p00 = __expf(s[2*q2][0]   - mn0), p01 = __expf(s[2*q2][1]   - mn0);
                float p02 = __expf(s[2*q2][2]   - mn1), p03 = __expf(s[2*q2][3]   - mn1);
                float p10 = __expf(s[2*q2+1][0] - mn0), p11 = __expf(s[2*q2+1][1] - mn0);
                float p12 = __expf(s[2*q2+1][2] - mn1), p13 = __expf(s[2*q2+1][3] - mn1);
                s0 += (p00 + p01) + (p10 + p11);
                s1 += (p02 + p03) + (p12 + p13);
                split2(p00, p01, ph[q2][0], pl[q2][0]);
                split2(p02, p03, ph[q2][1], pl[q2][1]);
                split2(p10, p11, ph[q2][2], pl[q2][2]);
                split2(p12, p13, ph[q2][3], pl[q2][3]);
            }
            s0 += __shfl_xor_sync(0xffffffffu, s0, 1);
            s0 += __shfl_xor_sync(0xffffffffu, s0, 2);
            s1 += __shfl_xor_sync(0xffffffffu, s1, 1);
            s1 += __shfl_xor_sync(0xffffffffu, s1, 2);
            l0 = l0 * c0r + s0;
            l1 = l1 * c1r + s1;

#pragma unroll
            for (int nt = 0; nt < 8; nt++) {
                o[nt][0] *= c0r; o[nt][1] *= c0r;
                o[nt][2] *= c1r; o[nt][3] *= c1r;
            }

            // ---- GEMM2: O += P @ V ----
#pragma unroll
            for (int nt = 0; nt < 8; nt++) {
                const u32 vb0 = bufb + 2 * PLANE * 4
                              + (u32)((nt * 8 + brow) * KTW + bsel * 4) * 4;
                u32 bh[4], bl[4];
                ldm_x4(bh, vb0);
                ldm_x4(bl, vb0 + PLANE * 4);
                mma16816(o[nt], ph[0], bh + 0);
                mma16816(o[nt], pl[0], bh + 0);
                mma16816(o[nt], ph[0], bl + 0);
                mma16816(o[nt], ph[1], bh + 2);
                mma16816(o[nt], pl[1], bh + 2);
                mma16816(o[nt], ph[1], bl + 2);
                ldm_x4(bh, vb0 + 64);
                ldm_x4(bl, vb0 + PLANE * 4 + 64);
                mma16816(o[nt], ph[2], bh + 0);
                mma16816(o[nt], pl[2], bh + 0);
                mma16816(o[nt], ph[2], bl + 0);
                mma16816(o[nt], ph[3], bh + 2);
                mma16816(o[nt], pl[3], bh + 2);
                mma16816(o[nt], ph[3], bl + 2);
            }
            barg(1 + gp);
        }

        // ---- 3-way merge (staging reuses group-0 buffers) ----
        __syncthreads();
        if (gp >= 1) {
            const int gi = gp - 1;
            float* mog = mo + gi * 64 * MO_STR;
            const int ra = r0, rb = r0 + 8;
#pragma unroll
            for (int nt = 0; nt < 8; nt++) {
                const int cc = nt * 8 + 2 * t;
                mog[ra * MO_STR + cc]     = o[nt][0];
                mog[ra * MO_STR + cc + 1] = o[nt][1];
                mog[rb * MO_STR + cc]     = o[nt][2];
                mog[rb * MO_STR + cc + 1] = o[nt][3];
            }
            if (t == 0) {
                mmv[gi * 64 + ra] = m0; mlv[gi * 64 + ra] = l0;
                mmv[gi * 64 + rb] = m1; mlv[gi * 64 + rb] = l1;
            }
        }
        __syncthreads();
        if (gp == 0) {
            const int ra = r0, rb = r0 + 8;
            const float m1a = mmv[ra],      l1a = mlv[ra];
            const float m2a = mmv[64 + ra], l2a = mlv[64 + ra];
            const float m1b = mmv[rb],      l1b = mlv[rb];
            const float m2b = mmv[64 + rb], l2b = mlv[64 + rb];
            const float msA = fmaxf(m0, fmaxf(m1a, m2a));
            const float msB = fmaxf(m1, fmaxf(m1b, m2b));
            const float f0A = __expf(m0 - msA), f1A = __expf(m1a - msA), f2A = __expf(m2a - msA);
            const float f0B = __expf(m1 - msB), f1B = __expf(m1b - msB), f2B = __expf(m2b - msB);
            const float invA = 1.f / (l0 * f0A + l1a * f1A + l2a * f2A);
            const float invB = 1.f / (l1 * f0B + l1b * f1B + l2b * f2B);
            const float* mo1 = mo;
            const float* mo2 = mo + 64 * MO_STR;
            float* orow0 = out + ((size_t)bb * TSEQ + qrow0 + ra) * HD;
            float* orow1 = out + ((size_t)bb * TSEQ + qrow0 + rb) * HD;
#pragma unroll
            for (int nt = 0; nt < 8; nt++) {
                const int cc = nt * 8 + 2 * t;
                float2 oa, ob;
                oa.x = (o[nt][0] * f0A + mo1[ra * MO_STR + cc]     * f1A
                                       + mo2[ra * MO_STR + cc]     * f2A) * invA;
                oa.y = (o[nt][1] * f0A + mo1[ra * MO_STR + cc + 1] * f1A
                                       + mo2[ra * MO_STR + cc + 1] * f2A) * invA;
                ob.x = (o[nt][2] * f0B + mo1[rb * MO_STR + cc]     * f1B
                                       + mo2[rb * MO_STR + cc]     * f2B) * invB;
                ob.y = (o[nt][3] * f0B + mo1[rb * MO_STR + cc + 1] * f1B
                                       + mo2[rb * MO_STR + cc + 1] * f2B) * invB;
                *reinterpret_cast<float2*>(orow0 + cc) = oa;
                *reinterpret_cast<float2*>(orow1 + cc) = ob;
            }
        }
        __syncthreads();
    }
}

// ---------------------------------------------------------------------------
extern "C" void kernel_launch(void* const* d_in, const int* in_sizes, int n_in,
                              void* d_out, int out_size)
{
    const float* x = (const float*)d_in[0];
    const float* W = (const float*)d_in[1];
    const float* b = (const float*)d_in[2];
    float* out = (float*)d_out;

    (void)in_sizes; (void)n_in; (void)out_size;

    static int attr_set = 0;
    if (!attr_set) {
        cudaFuncSetAttribute(attn_hmma_kernel,
                             cudaFuncAttributeMaxDynamicSharedMemorySize, ATTN_SMEM);
        cudaFuncSetAttribute(qkv_mma_kernel,
                             cudaFuncAttributeMaxDynamicSharedMemorySize, QKV_SMEM_BYTES);
        attr_set = 1;
    }

    wprep_kernel<<<(192 * CDIM + 255) / 256, 256>>>(W);
    qkv_mma_kernel<<<128, 256, QKV_SMEM_BYTES>>>(x, b);

    dim3 g2(16, BSZ);
    attn_hmma_kernel<<<g2, 384, ATTN_SMEM>>>(out);
}